// round 1
// baseline (speedup 1.0000x reference)
#include <cuda_runtime.h>
#include <cstdint>

#define B_ 2
#define S_ 2048
#define E_ 1024
#define H_ 16
#define D_ 64
#define M_ (B_*S_)   // 4096

// ---------------- scratch (device globals; no allocations allowed) ----------
static __device__ float g_Q[(size_t)B_*H_*S_*D_];     // [B,H,S,D]
static __device__ float g_K[(size_t)B_*H_*S_*D_];
static __device__ float g_V[(size_t)B_*H_*S_*D_];
static __device__ float g_m[(size_t)B_*H_*S_];        // softmax row max
static __device__ float g_linv[(size_t)B_*H_*S_];     // 1 / softmax row sum
static __device__ float g_ctx[2][(size_t)M_*E_];      // per-ksplit partial context

// ---------------- generic fp32 GEMM:  out = (A [+A2]) @ W^T + bias ----------
// A: [4096,1024] row-major, W: [1024,1024] row-major [n][k]
// bhsd=1: scatter output into [B,H,S,D]; bhsd=0: row-major [M,E]
__global__ void __launch_bounds__(256) sgemm_k(
    const float* __restrict__ A, const float* __restrict__ A2,
    const float* __restrict__ W, const float* __restrict__ bias,
    float* __restrict__ out, int bhsd)
{
    __shared__ float As[16][128];
    __shared__ float Bs[16][128];
    const int tid = threadIdx.x;
    const int tx = tid & 15, ty = tid >> 4;
    const int lr = tid >> 2;          // 0..63
    const int lk = (tid & 3) << 2;    // 0,4,8,12

    const float* Ap  = A + (size_t)(blockIdx.y*128 + lr) * E_ + lk;
    const float* Wp  = W + (size_t)(blockIdx.x*128 + lr) * E_ + lk;
    const float* A2p = A2 ? (A2 + (size_t)(blockIdx.y*128 + lr) * E_ + lk) : nullptr;

    float acc[8][8];
#pragma unroll
    for (int i = 0; i < 8; i++)
#pragma unroll
        for (int j = 0; j < 8; j++) acc[i][j] = 0.f;

    for (int k0 = 0; k0 < E_; k0 += 16) {
        float4 a0 = *(const float4*)(Ap + k0);
        float4 a1 = *(const float4*)(Ap + k0 + (size_t)64*E_);
        if (A2p) {
            float4 c0 = *(const float4*)(A2p + k0);
            float4 c1 = *(const float4*)(A2p + k0 + (size_t)64*E_);
            a0.x += c0.x; a0.y += c0.y; a0.z += c0.z; a0.w += c0.w;
            a1.x += c1.x; a1.y += c1.y; a1.z += c1.z; a1.w += c1.w;
        }
        float4 b0 = *(const float4*)(Wp + k0);
        float4 b1 = *(const float4*)(Wp + k0 + (size_t)64*E_);

        As[lk+0][lr] = a0.x; As[lk+1][lr] = a0.y; As[lk+2][lr] = a0.z; As[lk+3][lr] = a0.w;
        As[lk+0][lr+64] = a1.x; As[lk+1][lr+64] = a1.y; As[lk+2][lr+64] = a1.z; As[lk+3][lr+64] = a1.w;
        Bs[lk+0][lr] = b0.x; Bs[lk+1][lr] = b0.y; Bs[lk+2][lr] = b0.z; Bs[lk+3][lr] = b0.w;
        Bs[lk+0][lr+64] = b1.x; Bs[lk+1][lr+64] = b1.y; Bs[lk+2][lr+64] = b1.z; Bs[lk+3][lr+64] = b1.w;
        __syncthreads();

#pragma unroll
        for (int k = 0; k < 16; k++) {
            float4 af0 = *(const float4*)&As[k][ty*8];
            float4 af1 = *(const float4*)&As[k][ty*8+4];
            float4 bf0 = *(const float4*)&Bs[k][tx*8];
            float4 bf1 = *(const float4*)&Bs[k][tx*8+4];
            float av[8] = {af0.x,af0.y,af0.z,af0.w,af1.x,af1.y,af1.z,af1.w};
            float bv[8] = {bf0.x,bf0.y,bf0.z,bf0.w,bf1.x,bf1.y,bf1.z,bf1.w};
#pragma unroll
            for (int i = 0; i < 8; i++)
#pragma unroll
                for (int j = 0; j < 8; j++)
                    acc[i][j] = fmaf(av[i], bv[j], acc[i][j]);
        }
        __syncthreads();
    }

    const int m0 = blockIdx.y*128 + ty*8;
    const int n0 = blockIdx.x*128 + tx*8;
#pragma unroll
    for (int i = 0; i < 8; i++) {
        const int m = m0 + i;
        const int bb = m >> 11;
        const int ss = m & (S_-1);
#pragma unroll
        for (int j = 0; j < 8; j++) {
            const int n = n0 + j;
            const float v = acc[i][j] + bias[n];
            if (bhsd) {
                out[((size_t)(bb*H_ + (n >> 6))*S_ + ss)*D_ + (n & 63)] = v;
            } else {
                out[(size_t)m*E_ + n] = v;
            }
        }
    }
}

// ---------------- pass 1: softmax stats (row max, row sum) ------------------
// grid (S/64, H, B), 256 threads. Online max/sum over 16 k-tiles of 128.
__global__ void __launch_bounds__(256) attn_stats_k(const int* __restrict__ mask)
{
    extern __shared__ float sm[];
    float* Qs = sm;            // [64][64]  transposed: Qs[d*64 + r]
    float* Ks = sm + 64*64;    // [64][128] transposed: Ks[d*128 + c]

    const int tid = threadIdx.x;
    const int tx = tid & 15, ty = tid >> 4;
    const int q0 = blockIdx.x * 64;
    const int h  = blockIdx.y;
    const int b  = blockIdx.z;

    const float* Qg = g_Q + ((size_t)(b*H_ + h)*S_ + q0)*D_;
    const float* Kg = g_K + ((size_t)(b*H_ + h)*S_)*D_;

    {   // load Q tile transposed
        const int r  = tid >> 2;
        const int d0 = (tid & 3) * 16;
#pragma unroll
        for (int i = 0; i < 4; i++) {
            float4 v = *(const float4*)(Qg + (size_t)r*D_ + d0 + i*4);
            Qs[(d0+i*4+0)*64 + r] = v.x;
            Qs[(d0+i*4+1)*64 + r] = v.y;
            Qs[(d0+i*4+2)*64 + r] = v.z;
            Qs[(d0+i*4+3)*64 + r] = v.w;
        }
    }

    float m_i[4], l_i[4];
#pragma unroll
    for (int i = 0; i < 4; i++) { m_i[i] = -1e30f; l_i[i] = 0.f; }

    const int* mrow = mask + (size_t)b*S_*S_ + (size_t)(q0 + ty*4)*S_ + tx*8;

    for (int kt = 0; kt < 16; kt++) {
        const int k0 = kt * 128;
        __syncthreads();
        {   // load K tile transposed
            const int r  = tid >> 1;
            const int d0 = (tid & 1) * 32;
#pragma unroll
            for (int i = 0; i < 8; i++) {
                float4 v = *(const float4*)(Kg + (size_t)(k0+r)*D_ + d0 + i*4);
                Ks[(d0+i*4+0)*128 + r] = v.x;
                Ks[(d0+i*4+1)*128 + r] = v.y;
                Ks[(d0+i*4+2)*128 + r] = v.z;
                Ks[(d0+i*4+3)*128 + r] = v.w;
            }
        }
        __syncthreads();

        float s[4][8];
#pragma unroll
        for (int i = 0; i < 4; i++)
#pragma unroll
            for (int j = 0; j < 8; j++) s[i][j] = 0.f;

#pragma unroll 16
        for (int d = 0; d < 64; d++) {
            float4 af = *(const float4*)(Qs + d*64 + ty*4);
            float4 b0 = *(const float4*)(Ks + d*128 + tx*8);
            float4 b1 = *(const float4*)(Ks + d*128 + tx*8 + 4);
            float a[4] = {af.x, af.y, af.z, af.w};
            float bv[8] = {b0.x,b0.y,b0.z,b0.w,b1.x,b1.y,b1.z,b1.w};
#pragma unroll
            for (int i = 0; i < 4; i++)
#pragma unroll
                for (int j = 0; j < 8; j++)
                    s[i][j] = fmaf(a[i], bv[j], s[i][j]);
        }

#pragma unroll
        for (int i = 0; i < 4; i++) {
            int4 mk0 = *(const int4*)(mrow + (size_t)i*S_ + k0);
            int4 mk1 = *(const int4*)(mrow + (size_t)i*S_ + k0 + 4);
            int mk[8] = {mk0.x,mk0.y,mk0.z,mk0.w,mk1.x,mk1.y,mk1.z,mk1.w};
            float rmax = -1e30f;
#pragma unroll
            for (int j = 0; j < 8; j++) {
                float sv = mk[j] ? s[i][j]*0.125f : -1e9f;
                s[i][j] = sv;
                rmax = fmaxf(rmax, sv);
            }
#pragma unroll
            for (int off = 8; off > 0; off >>= 1)
                rmax = fmaxf(rmax, __shfl_xor_sync(0xffffffffu, rmax, off, 16));
            const float mnew = fmaxf(m_i[i], rmax);
            float sum = 0.f;
#pragma unroll
            for (int j = 0; j < 8; j++) sum += __expf(s[i][j] - mnew);
#pragma unroll
            for (int off = 8; off > 0; off >>= 1)
                sum += __shfl_xor_sync(0xffffffffu, sum, off, 16);
            l_i[i] = l_i[i] * __expf(m_i[i] - mnew) + sum;
            m_i[i] = mnew;
        }
    }

    if (tx == 0) {
#pragma unroll
        for (int i = 0; i < 4; i++) {
            const size_t idx = (size_t)(b*H_ + h)*S_ + q0 + ty*4 + i;
            g_m[idx]    = m_i[i];
            g_linv[idx] = 1.0f / l_i[i];
        }
    }
}

// ---------------- pass 2: probs, avg_attn accumulation, P@V -----------------
// grid (2 ksplit, S/64, B), 256 threads. Heads looped inside ->
// exclusive ownership of avg rows (no atomics); ctx split per ksplit.
__global__ void __launch_bounds__(256) attn_pass2_k(
    const int* __restrict__ mask, float* __restrict__ avg_out)
{
    extern __shared__ float sm[];
    float* Qs = sm;            // [64][64]  Qs[d*64 + r]
    float* Ks = sm + 4096;     // [64][128] Ks[d*128 + c]
    float* Vs = sm + 12288;    // [128][64] Vs[c*64 + d]
    float* Ps = sm + 20480;    // [128][68] Ps[c*68 + r]  (P transposed, padded)

    const int tid = threadIdx.x;
    const int tx = tid & 15, ty = tid >> 4;
    const int ks = blockIdx.x;
    const int q0 = blockIdx.y * 64;
    const int b  = blockIdx.z;
    float* ctx = &g_ctx[ks][0];

    for (int h = 0; h < H_; h++) {
        __syncthreads();   // previous head done with Qs
        const float* Qg = g_Q + ((size_t)(b*H_ + h)*S_ + q0)*D_;
        {   // load Q tile transposed
            const int r  = tid >> 2;
            const int d0 = (tid & 3) * 16;
#pragma unroll
            for (int i = 0; i < 4; i++) {
                float4 v = *(const float4*)(Qg + (size_t)r*D_ + d0 + i*4);
                Qs[(d0+i*4+0)*64 + r] = v.x;
                Qs[(d0+i*4+1)*64 + r] = v.y;
                Qs[(d0+i*4+2)*64 + r] = v.z;
                Qs[(d0+i*4+3)*64 + r] = v.w;
            }
        }
        float m_i[4], linv_i[4];
#pragma unroll
        for (int i = 0; i < 4; i++) {
            const size_t idx = (size_t)(b*H_ + h)*S_ + q0 + ty*4 + i;
            m_i[i]    = g_m[idx];
            linv_i[i] = g_linv[idx];
        }
        float o[4][4];
#pragma unroll
        for (int i = 0; i < 4; i++)
#pragma unroll
            for (int j = 0; j < 4; j++) o[i][j] = 0.f;

        for (int kt = 0; kt < 8; kt++) {
            const int k0 = (ks*8 + kt) * 128;
            __syncthreads();   // previous PV done with Ks/Vs/Ps
            {   // load K transposed + V direct
                const int r  = tid >> 1;
                const int d0 = (tid & 1) * 32;
                const float* Kg = g_K + ((size_t)(b*H_ + h)*S_ + k0 + r)*D_ + d0;
                const float* Vg = g_V + ((size_t)(b*H_ + h)*S_ + k0 + r)*D_ + d0;
#pragma unroll
                for (int i = 0; i < 8; i++) {
                    float4 kv = *(const float4*)(Kg + i*4);
                    Ks[(d0+i*4+0)*128 + r] = kv.x;
                    Ks[(d0+i*4+1)*128 + r] = kv.y;
                    Ks[(d0+i*4+2)*128 + r] = kv.z;
                    Ks[(d0+i*4+3)*128 + r] = kv.w;
                    *(float4*)(Vs + (size_t)r*64 + d0 + i*4) = *(const float4*)(Vg + i*4);
                }
            }
            __syncthreads();

            // ---- S = Q @ K^T ----
            float s[4][8];
#pragma unroll
            for (int i = 0; i < 4; i++)
#pragma unroll
                for (int j = 0; j < 8; j++) s[i][j] = 0.f;
#pragma unroll 16
            for (int d = 0; d < 64; d++) {
                float4 af = *(const float4*)(Qs + d*64 + ty*4);
                float4 b0 = *(const float4*)(Ks + d*128 + tx*8);
                float4 b1 = *(const float4*)(Ks + d*128 + tx*8 + 4);
                float a[4] = {af.x, af.y, af.z, af.w};
                float bv[8] = {b0.x,b0.y,b0.z,b0.w,b1.x,b1.y,b1.z,b1.w};
#pragma unroll
                for (int i = 0; i < 4; i++)
#pragma unroll
                    for (int j = 0; j < 8; j++)
                        s[i][j] = fmaf(a[i], bv[j], s[i][j]);
            }

            // ---- probs + avg_attn accumulation + Ps write ----
#pragma unroll
            for (int i = 0; i < 4; i++) {
                const size_t mbase = (size_t)b*S_*S_ + (size_t)(q0 + ty*4 + i)*S_ + k0 + tx*8;
                int4 mk0 = *(const int4*)(mask + mbase);
                int4 mk1 = *(const int4*)(mask + mbase + 4);
                int mk[8] = {mk0.x,mk0.y,mk0.z,mk0.w,mk1.x,mk1.y,mk1.z,mk1.w};
                float p[8];
#pragma unroll
                for (int j = 0; j < 8; j++)
                    p[j] = mk[j] ? (__expf(s[i][j]*0.125f - m_i[i]) * linv_i[i]) : 0.f;
#pragma unroll
                for (int j = 0; j < 8; j++)
                    Ps[(size_t)(tx*8 + j)*68 + ty*4 + i] = p[j];

                float* ap = avg_out + mbase;
                float4 w0 = make_float4(p[0]*0.0625f, p[1]*0.0625f, p[2]*0.0625f, p[3]*0.0625f);
                float4 w1 = make_float4(p[4]*0.0625f, p[5]*0.0625f, p[6]*0.0625f, p[7]*0.0625f);
                if (h != 0) {
                    float4 o0 = *(const float4*)ap;
                    float4 o1 = *(const float4*)(ap + 4);
                    w0.x += o0.x; w0.y += o0.y; w0.z += o0.z; w0.w += o0.w;
                    w1.x += o1.x; w1.y += o1.y; w1.z += o1.z; w1.w += o1.w;
                }
                *(float4*)ap       = w0;
                *(float4*)(ap + 4) = w1;
            }
            __syncthreads();

            // ---- O += P @ V ----
#pragma unroll 8
            for (int kk = 0; kk < 128; kk++) {
                float4 a = *(const float4*)(Ps + (size_t)kk*68 + ty*4);
                float4 v = *(const float4*)(Vs + (size_t)kk*64 + tx*4);
                float av[4] = {a.x, a.y, a.z, a.w};
                float vv[4] = {v.x, v.y, v.z, v.w};
#pragma unroll
                for (int i = 0; i < 4; i++)
#pragma unroll
                    for (int j = 0; j < 4; j++)
                        o[i][j] = fmaf(av[i], vv[j], o[i][j]);
            }
        }

        // write per-head context slice (exclusive per ksplit buffer)
#pragma unroll
        for (int i = 0; i < 4; i++) {
            float4 w = make_float4(o[i][0], o[i][1], o[i][2], o[i][3]);
            *(float4*)(ctx + (size_t)(b*S_ + q0 + ty*4 + i)*E_ + h*64 + tx*4) = w;
        }
    }
}

// ---------------- launch ----------------------------------------------------
extern "C" void kernel_launch(void* const* d_in, const int* in_sizes, int n_in,
                              void* d_out, int out_size)
{
    const float* query = (const float*)d_in[0];
    const float* key   = (const float*)d_in[1];
    const float* value = (const float*)d_in[2];
    const int*   mask  = (const int*)d_in[3];
    const float* Wq = (const float*)d_in[4];
    const float* bq = (const float*)d_in[5];
    const float* Wk = (const float*)d_in[6];
    const float* bk = (const float*)d_in[7];
    const float* Wv = (const float*)d_in[8];
    const float* bv = (const float*)d_in[9];
    const float* Wo = (const float*)d_in[10];
    const float* bo = (const float*)d_in[11];

    float* out = (float*)d_out;                      // [B,S,E]
    float* avg = out + (size_t)B_*S_*E_;             // [B,S,S]

    float *qp, *kp, *vp, *cp;
    cudaGetSymbolAddress((void**)&qp, g_Q);
    cudaGetSymbolAddress((void**)&kp, g_K);
    cudaGetSymbolAddress((void**)&vp, g_V);
    cudaGetSymbolAddress((void**)&cp, g_ctx);

    cudaFuncSetAttribute(attn_stats_k, cudaFuncAttributeMaxDynamicSharedMemorySize, 49152);
    cudaFuncSetAttribute(attn_pass2_k, cudaFuncAttributeMaxDynamicSharedMemorySize, 116736);

    dim3 gproj(E_/128, M_/128);   // (8, 32)
    sgemm_k<<<gproj, 256>>>(query, nullptr, Wq, bq, qp, 1);
    sgemm_k<<<gproj, 256>>>(key,   nullptr, Wk, bk, kp, 1);
    sgemm_k<<<gproj, 256>>>(value, nullptr, Wv, bv, vp, 1);

    attn_stats_k<<<dim3(S_/64, H_, B_), 256, 49152>>>(mask);
    attn_pass2_k<<<dim3(2, S_/64, B_), 256, 116736>>>(mask, avg);

    sgemm_k<<<gproj, 256>>>(cp, cp + (size_t)M_*E_, Wo, bo, out, 0);
}

// round 3
// speedup vs baseline: 1.1784x; 1.1784x over previous
#include <cuda_runtime.h>
#include <cstdint>

#define B_ 2
#define S_ 2048
#define E_ 1024
#define H_ 16
#define D_ 64
#define M_ (B_*S_)   // 4096

// ---------------- scratch (device globals; no allocations allowed) ----------
static __device__ float g_Q[(size_t)B_*H_*S_*D_];     // [B,H,S,D]
static __device__ float g_K[(size_t)B_*H_*S_*D_];
static __device__ float g_V[(size_t)B_*H_*S_*D_];
static __device__ float g_m[(size_t)B_*H_*S_];        // softmax row max
static __device__ float g_linv[(size_t)B_*H_*S_];     // 1 / softmax row sum
static __device__ float g_ctx[2][(size_t)M_*E_];      // per-ksplit partial context

// ===================== PTX helpers (sm_80-era only; no tcgen05) ==============
__device__ __forceinline__ uint32_t smem_u32(const void* p) {
    uint32_t a;
    asm("{ .reg .u64 t; cvta.to.shared.u64 t, %1; cvt.u32.u64 %0, t; }" : "=r"(a) : "l"(p));
    return a;
}
#define CPASYNC16(dst, src) \
    asm volatile("cp.async.cg.shared.global [%0], [%1], 16;" :: "r"(dst), "l"(src))
#define CPCOMMIT() asm volatile("cp.async.commit_group;" ::: "memory")

__device__ __forceinline__ uint32_t f2tf32(float x) {
    uint32_t r;
    asm("cvt.rna.tf32.f32 %0, %1;" : "=r"(r) : "f"(x));
    return r;
}
__device__ __forceinline__ void mma_tf32(float* c, const uint32_t* a, const uint32_t* b) {
    asm volatile(
        "mma.sync.aligned.m16n8k8.row.col.f32.tf32.tf32.f32 "
        "{%0,%1,%2,%3}, {%4,%5,%6,%7}, {%8,%9}, {%0,%1,%2,%3};"
        : "+f"(c[0]), "+f"(c[1]), "+f"(c[2]), "+f"(c[3])
        : "r"(a[0]), "r"(a[1]), "r"(a[2]), "r"(a[3]), "r"(b[0]), "r"(b[1]));
}

// ===================== tf32 mma.sync GEMM: out = A @ W^T + bias ==============
// A: [4096,1024] f32 row-major, W: [1024,1024] f32 row-major [n][k].
// BM=128, BN=128, BK=32, 8 warps (warp tile 32x64), double-buffered cp.async.
// qkv=1: scatter output into [B,H,S,D]; qkv=0: row-major [M,E].
#define BK_ 32
#define PADK 36   // pad to 144B row stride: 16B-aligned, conflict-free
#define GEMM_SMEM_BYTES (2 * 2 * 128 * PADK * 4)   // 73728

__global__ void __launch_bounds__(256, 1)
gemm_tf32_k(const float* __restrict__ A, const float* __restrict__ W,
            const float* __restrict__ bias, float* __restrict__ out, int qkv)
{
    extern __shared__ float sgm[];
    float (*As)[128][PADK] = (float(*)[128][PADK])sgm;                   // [2][128][36]
    float (*Ws)[128][PADK] = (float(*)[128][PADK])(sgm + 2*128*PADK);    // [2][128][36]

    const int tid = threadIdx.x;
    const int lane = tid & 31, wid = tid >> 5;
    const int wm = (wid & 3) * 32;    // warp row offset in block tile
    const int wn = (wid >> 2) * 64;   // warp col offset in block tile
    const int m0 = blockIdx.y * 128;
    const int n0 = blockIdx.x * 128;

    const float* Abase = A + (size_t)m0 * E_;
    const float* Wbase = W + (size_t)n0 * E_;

    const int r_ld = tid >> 1;             // 0..127
    const int c_ld = (tid & 1) * 16;       // 0 or 16 (floats)

    // ---- stage loader: 128 rows x 32 floats for A and W tiles ----
    auto load_stage = [&](int it, int buf) {
        const float* Ap = Abase + (size_t)r_ld * E_ + it * BK_ + c_ld;
        const float* Wp = Wbase + (size_t)r_ld * E_ + it * BK_ + c_ld;
        uint32_t da = smem_u32(&As[buf][r_ld][c_ld]);
        uint32_t dw = smem_u32(&Ws[buf][r_ld][c_ld]);
#pragma unroll
        for (int i = 0; i < 4; i++) {
            CPASYNC16(da + i * 16, Ap + i * 4);
            CPASYNC16(dw + i * 16, Wp + i * 4);
        }
        CPCOMMIT();
    };

    float acc[2][8][4];
#pragma unroll
    for (int mi = 0; mi < 2; mi++)
#pragma unroll
        for (int ni = 0; ni < 8; ni++)
#pragma unroll
            for (int j = 0; j < 4; j++) acc[mi][ni][j] = 0.f;

    const int NT = E_ / BK_;   // 32
    load_stage(0, 0);

    const int qr = lane >> 2;     // 0..7
    const int qc = lane & 3;      // 0..3

    for (int it = 0; it < NT; it++) {
        if (it + 1 < NT) load_stage(it + 1, (it + 1) & 1);
        if (it + 1 < NT) asm volatile("cp.async.wait_group 1;" ::: "memory");
        else             asm volatile("cp.async.wait_group 0;" ::: "memory");
        __syncthreads();

        const int buf = it & 1;
#pragma unroll
        for (int ks = 0; ks < 4; ks++) {
            const int k0 = ks * 8;
            uint32_t a[2][4], b[8][2];
#pragma unroll
            for (int mi = 0; mi < 2; mi++) {
                const int r = wm + mi * 16 + qr;
                a[mi][0] = f2tf32(As[buf][r][k0 + qc]);
                a[mi][1] = f2tf32(As[buf][r + 8][k0 + qc]);
                a[mi][2] = f2tf32(As[buf][r][k0 + qc + 4]);
                a[mi][3] = f2tf32(As[buf][r + 8][k0 + qc + 4]);
            }
#pragma unroll
            for (int ni = 0; ni < 8; ni++) {
                const int n = wn + ni * 8 + qr;
                b[ni][0] = f2tf32(Ws[buf][n][k0 + qc]);
                b[ni][1] = f2tf32(Ws[buf][n][k0 + qc + 4]);
            }
#pragma unroll
            for (int mi = 0; mi < 2; mi++)
#pragma unroll
                for (int ni = 0; ni < 8; ni++)
                    mma_tf32(acc[mi][ni], a[mi], b[ni]);
        }
        __syncthreads();
    }

    // ---- epilogue: registers -> gmem with bias ----
#pragma unroll
    for (int mi = 0; mi < 2; mi++) {
        const int r0 = m0 + wm + mi * 16 + qr;
#pragma unroll
        for (int ni = 0; ni < 8; ni++) {
            const int n = n0 + wn + ni * 8 + 2 * qc;
            const float b0 = bias[n], b1 = bias[n + 1];
            float2 v0 = make_float2(acc[mi][ni][0] + b0, acc[mi][ni][1] + b1);
            float2 v1 = make_float2(acc[mi][ni][2] + b0, acc[mi][ni][3] + b1);
            if (qkv) {
                const int h = n >> 6, d = n & 63;
                const int bb0 = r0 >> 11, ss0 = r0 & (S_ - 1);
                const int r1 = r0 + 8;
                const int bb1 = r1 >> 11, ss1 = r1 & (S_ - 1);
                *(float2*)(out + (((size_t)(bb0 * H_ + h) * S_ + ss0) * D_ + d)) = v0;
                *(float2*)(out + (((size_t)(bb1 * H_ + h) * S_ + ss1) * D_ + d)) = v1;
            } else {
                *(float2*)(out + (size_t)r0 * E_ + n) = v0;
                *(float2*)(out + (size_t)(r0 + 8) * E_ + n) = v1;
            }
        }
    }
}

// ---------------- elementwise add: a += b (float4) --------------------------
__global__ void __launch_bounds__(256) add_k(float* __restrict__ a, const float* __restrict__ b)
{
    const size_t i = ((size_t)blockIdx.x * 256 + threadIdx.x) * 4;
    float4 x = *(const float4*)(a + i);
    float4 y = *(const float4*)(b + i);
    x.x += y.x; x.y += y.y; x.z += y.z; x.w += y.w;
    *(float4*)(a + i) = x;
}

// ---------------- pass 1: softmax stats (row max, row sum) ------------------
__global__ void __launch_bounds__(256) attn_stats_k(const int* __restrict__ mask)
{
    extern __shared__ float sm[];
    float* Qs = sm;            // [64][64]  transposed: Qs[d*64 + r]
    float* Ks = sm + 64*64;    // [64][128] transposed: Ks[d*128 + c]

    const int tid = threadIdx.x;
    const int tx = tid & 15, ty = tid >> 4;
    const int q0 = blockIdx.x * 64;
    const int h  = blockIdx.y;
    const int b  = blockIdx.z;

    const float* Qg = g_Q + ((size_t)(b*H_ + h)*S_ + q0)*D_;
    const float* Kg = g_K + ((size_t)(b*H_ + h)*S_)*D_;

    {   // load Q tile transposed
        const int r  = tid >> 2;
        const int d0 = (tid & 3) * 16;
#pragma unroll
        for (int i = 0; i < 4; i++) {
            float4 v = *(const float4*)(Qg + (size_t)r*D_ + d0 + i*4);
            Qs[(d0+i*4+0)*64 + r] = v.x;
            Qs[(d0+i*4+1)*64 + r] = v.y;
            Qs[(d0+i*4+2)*64 + r] = v.z;
            Qs[(d0+i*4+3)*64 + r] = v.w;
        }
    }

    float m_i[4], l_i[4];
#pragma unroll
    for (int i = 0; i < 4; i++) { m_i[i] = -1e30f; l_i[i] = 0.f; }

    const int* mrow = mask + (size_t)b*S_*S_ + (size_t)(q0 + ty*4)*S_ + tx*8;

    for (int kt = 0; kt < 16; kt++) {
        const int k0 = kt * 128;
        __syncthreads();
        {   // load K tile transposed
            const int r  = tid >> 1;
            const int d0 = (tid & 1) * 32;
#pragma unroll
            for (int i = 0; i < 8; i++) {
                float4 v = *(const float4*)(Kg + (size_t)(k0+r)*D_ + d0 + i*4);
                Ks[(d0+i*4+0)*128 + r] = v.x;
                Ks[(d0+i*4+1)*128 + r] = v.y;
                Ks[(d0+i*4+2)*128 + r] = v.z;
                Ks[(d0+i*4+3)*128 + r] = v.w;
            }
        }
        __syncthreads();

        float s[4][8];
#pragma unroll
        for (int i = 0; i < 4; i++)
#pragma unroll
            for (int j = 0; j < 8; j++) s[i][j] = 0.f;

#pragma unroll 16
        for (int d = 0; d < 64; d++) {
            float4 af = *(const float4*)(Qs + d*64 + ty*4);
            float4 b0 = *(const float4*)(Ks + d*128 + tx*8);
            float4 b1 = *(const float4*)(Ks + d*128 + tx*8 + 4);
            float a[4] = {af.x, af.y, af.z, af.w};
            float bv[8] = {b0.x,b0.y,b0.z,b0.w,b1.x,b1.y,b1.z,b1.w};
#pragma unroll
            for (int i = 0; i < 4; i++)
#pragma unroll
                for (int j = 0; j < 8; j++)
                    s[i][j] = fmaf(a[i], bv[j], s[i][j]);
        }

#pragma unroll
        for (int i = 0; i < 4; i++) {
            int4 mk0 = *(const int4*)(mrow + (size_t)i*S_ + k0);
            int4 mk1 = *(const int4*)(mrow + (size_t)i*S_ + k0 + 4);
            int mk[8] = {mk0.x,mk0.y,mk0.z,mk0.w,mk1.x,mk1.y,mk1.z,mk1.w};
            float rmax = -1e30f;
#pragma unroll
            for (int j = 0; j < 8; j++) {
                float sv = mk[j] ? s[i][j]*0.125f : -1e9f;
                s[i][j] = sv;
                rmax = fmaxf(rmax, sv);
            }
#pragma unroll
            for (int off = 8; off > 0; off >>= 1)
                rmax = fmaxf(rmax, __shfl_xor_sync(0xffffffffu, rmax, off, 16));
            const float mnew = fmaxf(m_i[i], rmax);
            float sum = 0.f;
#pragma unroll
            for (int j = 0; j < 8; j++) sum += __expf(s[i][j] - mnew);
#pragma unroll
            for (int off = 8; off > 0; off >>= 1)
                sum += __shfl_xor_sync(0xffffffffu, sum, off, 16);
            l_i[i] = l_i[i] * __expf(m_i[i] - mnew) + sum;
            m_i[i] = mnew;
        }
    }

    if (tx == 0) {
#pragma unroll
        for (int i = 0; i < 4; i++) {
            const size_t idx = (size_t)(b*H_ + h)*S_ + q0 + ty*4 + i;
            g_m[idx]    = m_i[i];
            g_linv[idx] = 1.0f / l_i[i];
        }
    }
}

// ---------------- pass 2: probs, avg_attn accumulation, P@V -----------------
__global__ void __launch_bounds__(256) attn_pass2_k(
    const int* __restrict__ mask, float* __restrict__ avg_out)
{
    extern __shared__ float sm[];
    float* Qs = sm;            // [64][64]  Qs[d*64 + r]
    float* Ks = sm + 4096;     // [64][128] Ks[d*128 + c]
    float* Vs = sm + 12288;    // [128][64] Vs[c*64 + d]
    float* Ps = sm + 20480;    // [128][68] Ps[c*68 + r]  (P transposed, padded)

    const int tid = threadIdx.x;
    const int tx = tid & 15, ty = tid >> 4;
    const int ks = blockIdx.x;
    const int q0 = blockIdx.y * 64;
    const int b  = blockIdx.z;
    float* ctx = &g_ctx[ks][0];

    for (int h = 0; h < H_; h++) {
        __syncthreads();   // previous head done with Qs
        const float* Qg = g_Q + ((size_t)(b*H_ + h)*S_ + q0)*D_;
        {   // load Q tile transposed
            const int r  = tid >> 2;
            const int d0 = (tid & 3) * 16;
#pragma unroll
            for (int i = 0; i < 4; i++) {
                float4 v = *(const float4*)(Qg + (size_t)r*D_ + d0 + i*4);
                Qs[(d0+i*4+0)*64 + r] = v.x;
                Qs[(d0+i*4+1)*64 + r] = v.y;
                Qs[(d0+i*4+2)*64 + r] = v.z;
                Qs[(d0+i*4+3)*64 + r] = v.w;
            }
        }
        float m_i[4], linv_i[4];
#pragma unroll
        for (int i = 0; i < 4; i++) {
            const size_t idx = (size_t)(b*H_ + h)*S_ + q0 + ty*4 + i;
            m_i[i]    = g_m[idx];
            linv_i[i] = g_linv[idx];
        }
        float o[4][4];
#pragma unroll
        for (int i = 0; i < 4; i++)
#pragma unroll
            for (int j = 0; j < 4; j++) o[i][j] = 0.f;

        for (int kt = 0; kt < 8; kt++) {
            const int k0 = (ks*8 + kt) * 128;
            __syncthreads();   // previous PV done with Ks/Vs/Ps
            {   // load K transposed + V direct
                const int r  = tid >> 1;
                const int d0 = (tid & 1) * 32;
                const float* Kg = g_K + ((size_t)(b*H_ + h)*S_ + k0 + r)*D_ + d0;
                const float* Vg = g_V + ((size_t)(b*H_ + h)*S_ + k0 + r)*D_ + d0;
#pragma unroll
                for (int i = 0; i < 8; i++) {
                    float4 kv = *(const float4*)(Kg + i*4);
                    Ks[(d0+i*4+0)*128 + r] = kv.x;
                    Ks[(d0+i*4+1)*128 + r] = kv.y;
                    Ks[(d0+i*4+2)*128 + r] = kv.z;
                    Ks[(d0+i*4+3)*128 + r] = kv.w;
                    *(float4*)(Vs + (size_t)r*64 + d0 + i*4) = *(const float4*)(Vg + i*4);
                }
            }
            __syncthreads();

            // ---- S = Q @ K^T ----
            float s[4][8];
#pragma unroll
            for (int i = 0; i < 4; i++)
#pragma unroll
                for (int j = 0; j < 8; j++) s[i][j] = 0.f;
#pragma unroll 16
            for (int d = 0; d < 64; d++) {
                float4 af = *(const float4*)(Qs + d*64 + ty*4);
                float4 b0 = *(const float4*)(Ks + d*128 + tx*8);
                float4 b1 = *(const float4*)(Ks + d*128 + tx*8 + 4);
                float a[4] = {af.x, af.y, af.z, af.w};
                float bv[8] = {b0.x,b0.y,b0.z,b0.w,b1.x,b1.y,b1.z,b1.w};
#pragma unroll
                for (int i = 0; i < 4; i++)
#pragma unroll
                    for (int j = 0; j < 8; j++)
                        s[i][j] = fmaf(a[i], bv[j], s[i][j]);
            }

            // ---- probs + avg_attn accumulation + Ps write ----
#pragma unroll
            for (int i = 0; i < 4; i++) {
                const size_t mbase = (size_t)b*S_*S_ + (size_t)(q0 + ty*4 + i)*S_ + k0 + tx*8;
                int4 mk0 = *(const int4*)(mask + mbase);
                int4 mk1 = *(const int4*)(mask + mbase + 4);
                int mk[8] = {mk0.x,mk0.y,mk0.z,mk0.w,mk1.x,mk1.y,mk1.z,mk1.w};
                float p[8];
#pragma unroll
                for (int j = 0; j < 8; j++)
                    p[j] = mk[j] ? (__expf(s[i][j]*0.125f - m_i[i]) * linv_i[i]) : 0.f;
#pragma unroll
                for (int j = 0; j < 8; j++)
                    Ps[(size_t)(tx*8 + j)*68 + ty*4 + i] = p[j];

                float* ap = avg_out + mbase;
                float4 w0 = make_float4(p[0]*0.0625f, p[1]*0.0625f, p[2]*0.0625f, p[3]*0.0625f);
                float4 w1 = make_float4(p[4]*0.0625f, p[5]*0.0625f, p[6]*0.0625f, p[7]*0.0625f);
                if (h != 0) {
                    float4 o0 = *(const float4*)ap;
                    float4 o1 = *(const float4*)(ap + 4);
                    w0.x += o0.x; w0.y += o0.y; w0.z += o0.z; w0.w += o0.w;
                    w1.x += o1.x; w1.y += o1.y; w1.z += o1.z; w1.w += o1.w;
                }
                *(float4*)ap       = w0;
                *(float4*)(ap + 4) = w1;
            }
            __syncthreads();

            // ---- O += P @ V ----
#pragma unroll 8
            for (int kk = 0; kk < 128; kk++) {
                float4 a = *(const float4*)(Ps + (size_t)kk*68 + ty*4);
                float4 v = *(const float4*)(Vs + (size_t)kk*64 + tx*4);
                float av[4] = {a.x, a.y, a.z, a.w};
                float vv[4] = {v.x, v.y, v.z, v.w};
#pragma unroll
                for (int i = 0; i < 4; i++)
#pragma unroll
                    for (int j = 0; j < 4; j++)
                        o[i][j] = fmaf(av[i], vv[j], o[i][j]);
            }
        }

        // write per-head context slice (exclusive per ksplit buffer)
#pragma unroll
        for (int i = 0; i < 4; i++) {
            float4 w = make_float4(o[i][0], o[i][1], o[i][2], o[i][3]);
            *(float4*)(ctx + (size_t)(b*S_ + q0 + ty*4 + i)*E_ + h*64 + tx*4) = w;
        }
    }
}

// ---------------- launch ----------------------------------------------------
extern "C" void kernel_launch(void* const* d_in, const int* in_sizes, int n_in,
                              void* d_out, int out_size)
{
    const float* query = (const float*)d_in[0];
    const float* key   = (const float*)d_in[1];
    const float* value = (const float*)d_in[2];
    const int*   mask  = (const int*)d_in[3];
    const float* Wq = (const float*)d_in[4];
    const float* bq = (const float*)d_in[5];
    const float* Wk = (const float*)d_in[6];
    const float* bk = (const float*)d_in[7];
    const float* Wv = (const float*)d_in[8];
    const float* bv = (const float*)d_in[9];
    const float* Wo = (const float*)d_in[10];
    const float* bo = (const float*)d_in[11];

    float* out = (float*)d_out;                      // [B,S,E]
    float* avg = out + (size_t)B_*S_*E_;             // [B,S,S]

    float *qp, *kp, *vp, *cp;
    cudaGetSymbolAddress((void**)&qp, g_Q);
    cudaGetSymbolAddress((void**)&kp, g_K);
    cudaGetSymbolAddress((void**)&vp, g_V);
    cudaGetSymbolAddress((void**)&cp, g_ctx);

    cudaFuncSetAttribute(gemm_tf32_k, cudaFuncAttributeMaxDynamicSharedMemorySize, GEMM_SMEM_BYTES);
    cudaFuncSetAttribute(attn_stats_k, cudaFuncAttributeMaxDynamicSharedMemorySize, 49152);
    cudaFuncSetAttribute(attn_pass2_k, cudaFuncAttributeMaxDynamicSharedMemorySize, 116736);

    dim3 ggemm(E_/128, M_/128);   // (8, 32)
    gemm_tf32_k<<<ggemm, 256, GEMM_SMEM_BYTES>>>(query, Wq, bq, qp, 1);
    gemm_tf32_k<<<ggemm, 256, GEMM_SMEM_BYTES>>>(key,   Wk, bk, kp, 1);
    gemm_tf32_k<<<ggemm, 256, GEMM_SMEM_BYTES>>>(value, Wv, bv, vp, 1);

    attn_stats_k<<<dim3(S_/64, H_, B_), 256, 49152>>>(mask);
    attn_pass2_k<<<dim3(2, S_/64, B_), 256, 116736>>>(mask, avg);

    add_k<<<(M_*E_)/1024, 256>>>(cp, cp + (size_t)M_*E_);
    gemm_tf32_k<<<ggemm, 256, GEMM_SMEM_BYTES>>>(cp, Wo, bo, out, 0);
}

// round 4
// speedup vs baseline: 1.2700x; 1.0777x over previous
#include <cuda_runtime.h>
#include <cuda_bf16.h>
#include <cstdint>

#define B_ 2
#define S_ 2048
#define E_ 1024
#define H_ 16
#define D_ 64
#define M_ (B_*S_)   // 4096

// ---------------- scratch (device globals; no allocations allowed) ----------
static __device__ float g_Q[(size_t)B_*H_*S_*D_];     // [B,H,S,D]
static __device__ float g_K[(size_t)B_*H_*S_*D_];
static __device__ float g_V[(size_t)B_*H_*S_*D_];
static __device__ float g_linv[(size_t)B_*H_*S_];     // 1 / softmax row sum
static __device__ float g_T[(size_t)B_*H_*S_*S_];     // exp(masked scaled scores), 512 MB
static __device__ float g_ctx[4][(size_t)M_*E_];      // per-ksplit partial context

// ===================== PTX helpers (sm_80-era only; no tcgen05) ==============
__device__ __forceinline__ uint32_t smem_u32(const void* p) {
    uint32_t a;
    asm("{ .reg .u64 t; cvta.to.shared.u64 t, %1; cvt.u32.u64 %0, t; }" : "=r"(a) : "l"(p));
    return a;
}
#define CPASYNC16(dst, src) \
    asm volatile("cp.async.cg.shared.global [%0], [%1], 16;" :: "r"(dst), "l"(src))
#define CPCOMMIT() asm volatile("cp.async.commit_group;" ::: "memory")

__device__ __forceinline__ uint32_t f2tf32(float x) {
    uint32_t r;
    asm("cvt.rna.tf32.f32 %0, %1;" : "=r"(r) : "f"(x));
    return r;
}
__device__ __forceinline__ void mma_tf32(float* c, const uint32_t* a, const uint32_t* b) {
    asm volatile(
        "mma.sync.aligned.m16n8k8.row.col.f32.tf32.tf32.f32 "
        "{%0,%1,%2,%3}, {%4,%5,%6,%7}, {%8,%9}, {%0,%1,%2,%3};"
        : "+f"(c[0]), "+f"(c[1]), "+f"(c[2]), "+f"(c[3])
        : "r"(a[0]), "r"(a[1]), "r"(a[2]), "r"(a[3]), "r"(b[0]), "r"(b[1]));
}
__device__ __forceinline__ void mma_bf16(float* c, const uint32_t* a, uint32_t b0, uint32_t b1) {
    asm volatile(
        "mma.sync.aligned.m16n8k16.row.col.f32.bf16.bf16.f32 "
        "{%0,%1,%2,%3}, {%4,%5,%6,%7}, {%8,%9}, {%0,%1,%2,%3};"
        : "+f"(c[0]), "+f"(c[1]), "+f"(c[2]), "+f"(c[3])
        : "r"(a[0]), "r"(a[1]), "r"(a[2]), "r"(a[3]), "r"(b0), "r"(b1));
}
__device__ __forceinline__ uint32_t pack_bf2(float x, float y) {
    __nv_bfloat16 hx = __float2bfloat16(x), hy = __float2bfloat16(y);
    return (uint32_t)__bfloat16_as_ushort(hx) | ((uint32_t)__bfloat16_as_ushort(hy) << 16);
}

// ===================== tf32 mma.sync GEMM: out = A @ W^T + bias ==============
#define BK_ 32
#define PADK 36
#define GEMM_SMEM_BYTES (2 * 2 * 128 * PADK * 4)   // 73728

__global__ void __launch_bounds__(256, 1)
gemm_tf32_k(const float* __restrict__ A, const float* __restrict__ W,
            const float* __restrict__ bias, float* __restrict__ out, int qkv)
{
    extern __shared__ float sgm[];
    float (*As)[128][PADK] = (float(*)[128][PADK])sgm;
    float (*Ws)[128][PADK] = (float(*)[128][PADK])(sgm + 2*128*PADK);

    const int tid = threadIdx.x;
    const int lane = tid & 31, wid = tid >> 5;
    const int wm = (wid & 3) * 32;
    const int wn = (wid >> 2) * 64;
    const int m0 = blockIdx.y * 128;
    const int n0 = blockIdx.x * 128;

    const float* Abase = A + (size_t)m0 * E_;
    const float* Wbase = W + (size_t)n0 * E_;

    const int r_ld = tid >> 1;
    const int c_ld = (tid & 1) * 16;

    auto load_stage = [&](int it, int buf) {
        const float* Ap = Abase + (size_t)r_ld * E_ + it * BK_ + c_ld;
        const float* Wp = Wbase + (size_t)r_ld * E_ + it * BK_ + c_ld;
        uint32_t da = smem_u32(&As[buf][r_ld][c_ld]);
        uint32_t dw = smem_u32(&Ws[buf][r_ld][c_ld]);
#pragma unroll
        for (int i = 0; i < 4; i++) {
            CPASYNC16(da + i * 16, Ap + i * 4);
            CPASYNC16(dw + i * 16, Wp + i * 4);
        }
        CPCOMMIT();
    };

    float acc[2][8][4];
#pragma unroll
    for (int mi = 0; mi < 2; mi++)
#pragma unroll
        for (int ni = 0; ni < 8; ni++)
#pragma unroll
            for (int j = 0; j < 4; j++) acc[mi][ni][j] = 0.f;

    const int NT = E_ / BK_;
    load_stage(0, 0);

    const int qr = lane >> 2;
    const int qc = lane & 3;

    for (int it = 0; it < NT; it++) {
        if (it + 1 < NT) load_stage(it + 1, (it + 1) & 1);
        if (it + 1 < NT) asm volatile("cp.async.wait_group 1;" ::: "memory");
        else             asm volatile("cp.async.wait_group 0;" ::: "memory");
        __syncthreads();

        const int buf = it & 1;
#pragma unroll
        for (int ks = 0; ks < 4; ks++) {
            const int k0 = ks * 8;
            uint32_t a[2][4], b[8][2];
#pragma unroll
            for (int mi = 0; mi < 2; mi++) {
                const int r = wm + mi * 16 + qr;
                a[mi][0] = f2tf32(As[buf][r][k0 + qc]);
                a[mi][1] = f2tf32(As[buf][r + 8][k0 + qc]);
                a[mi][2] = f2tf32(As[buf][r][k0 + qc + 4]);
                a[mi][3] = f2tf32(As[buf][r + 8][k0 + qc + 4]);
            }
#pragma unroll
            for (int ni = 0; ni < 8; ni++) {
                const int n = wn + ni * 8 + qr;
                b[ni][0] = f2tf32(Ws[buf][n][k0 + qc]);
                b[ni][1] = f2tf32(Ws[buf][n][k0 + qc + 4]);
            }
#pragma unroll
            for (int mi = 0; mi < 2; mi++)
#pragma unroll
                for (int ni = 0; ni < 8; ni++)
                    mma_tf32(acc[mi][ni], a[mi], b[ni]);
        }
        __syncthreads();
    }

#pragma unroll
    for (int mi = 0; mi < 2; mi++) {
        const int r0 = m0 + wm + mi * 16 + qr;
#pragma unroll
        for (int ni = 0; ni < 8; ni++) {
            const int n = n0 + wn + ni * 8 + 2 * qc;
            const float b0 = bias[n], b1 = bias[n + 1];
            float2 v0 = make_float2(acc[mi][ni][0] + b0, acc[mi][ni][1] + b1);
            float2 v1 = make_float2(acc[mi][ni][2] + b0, acc[mi][ni][3] + b1);
            if (qkv) {
                const int h = n >> 6, d = n & 63;
                const int bb0 = r0 >> 11, ss0 = r0 & (S_ - 1);
                const int r1 = r0 + 8;
                const int bb1 = r1 >> 11, ss1 = r1 & (S_ - 1);
                *(float2*)(out + (((size_t)(bb0 * H_ + h) * S_ + ss0) * D_ + d)) = v0;
                *(float2*)(out + (((size_t)(bb1 * H_ + h) * S_ + ss1) * D_ + d)) = v1;
            } else {
                *(float2*)(out + (size_t)r0 * E_ + n) = v0;
                *(float2*)(out + (size_t)(r0 + 8) * E_ + n) = v1;
            }
        }
    }
}

// ---------------- ctx0 += ctx1 + ctx2 + ctx3 --------------------------------
__global__ void __launch_bounds__(256) add4_k()
{
    const size_t i = ((size_t)blockIdx.x * 256 + threadIdx.x) * 4;
    float4 x = *(const float4*)(&g_ctx[0][i]);
    float4 a = *(const float4*)(&g_ctx[1][i]);
    float4 b = *(const float4*)(&g_ctx[2][i]);
    float4 c = *(const float4*)(&g_ctx[3][i]);
    x.x += a.x + b.x + c.x; x.y += a.y + b.y + c.y;
    x.z += a.z + b.z + c.z; x.w += a.w + b.w + c.w;
    *(float4*)(&g_ctx[0][i]) = x;
}

// ---------------- pass 1: QK^T (fp32 FFMA) + exp + row-sum -------------------
// grid (S/64, H, B), 256 threads. Stores t = mask ? exp(s/8) : 0 into g_T.
__global__ void __launch_bounds__(256) attn_exp_k(const int* __restrict__ mask)
{
    extern __shared__ float sm[];
    float* Qs = sm;            // [64][64]  transposed: Qs[d*64 + r]
    float* Ks = sm + 64*64;    // [64][128] transposed: Ks[d*128 + c]

    const int tid = threadIdx.x;
    const int tx = tid & 15, ty = tid >> 4;
    const int q0 = blockIdx.x * 64;
    const int h  = blockIdx.y;
    const int b  = blockIdx.z;

    const float* Qg = g_Q + ((size_t)(b*H_ + h)*S_ + q0)*D_;
    const float* Kg = g_K + ((size_t)(b*H_ + h)*S_)*D_;

    {   // load Q tile transposed
        const int r  = tid >> 2;
        const int d0 = (tid & 3) * 16;
#pragma unroll
        for (int i = 0; i < 4; i++) {
            float4 v = *(const float4*)(Qg + (size_t)r*D_ + d0 + i*4);
            Qs[(d0+i*4+0)*64 + r] = v.x;
            Qs[(d0+i*4+1)*64 + r] = v.y;
            Qs[(d0+i*4+2)*64 + r] = v.z;
            Qs[(d0+i*4+3)*64 + r] = v.w;
        }
    }

    float l_i[4] = {0.f, 0.f, 0.f, 0.f};
    const int* mrow = mask + (size_t)b*S_*S_ + (size_t)(q0 + ty*4)*S_ + tx*8;
    float* Trow = g_T + ((size_t)(b*H_ + h)*S_ + q0 + ty*4)*S_ + tx*8;

    for (int kt = 0; kt < 16; kt++) {
        const int k0 = kt * 128;
        __syncthreads();
        {   // load K tile transposed
            const int r  = tid >> 1;
            const int d0 = (tid & 1) * 32;
#pragma unroll
            for (int i = 0; i < 8; i++) {
                float4 v = *(const float4*)(Kg + (size_t)(k0+r)*D_ + d0 + i*4);
                Ks[(d0+i*4+0)*128 + r] = v.x;
                Ks[(d0+i*4+1)*128 + r] = v.y;
                Ks[(d0+i*4+2)*128 + r] = v.z;
                Ks[(d0+i*4+3)*128 + r] = v.w;
            }
        }
        __syncthreads();

        float s[4][8];
#pragma unroll
        for (int i = 0; i < 4; i++)
#pragma unroll
            for (int j = 0; j < 8; j++) s[i][j] = 0.f;

#pragma unroll 16
        for (int d = 0; d < 64; d++) {
            float4 af = *(const float4*)(Qs + d*64 + ty*4);
            float4 b0 = *(const float4*)(Ks + d*128 + tx*8);
            float4 b1 = *(const float4*)(Ks + d*128 + tx*8 + 4);
            float a[4] = {af.x, af.y, af.z, af.w};
            float bv[8] = {b0.x,b0.y,b0.z,b0.w,b1.x,b1.y,b1.z,b1.w};
#pragma unroll
            for (int i = 0; i < 4; i++)
#pragma unroll
                for (int j = 0; j < 8; j++)
                    s[i][j] = fmaf(a[i], bv[j], s[i][j]);
        }

#pragma unroll
        for (int i = 0; i < 4; i++) {
            int4 mk0 = *(const int4*)(mrow + (size_t)i*S_ + k0);
            int4 mk1 = *(const int4*)(mrow + (size_t)i*S_ + k0 + 4);
            int mk[8] = {mk0.x,mk0.y,mk0.z,mk0.w,mk1.x,mk1.y,mk1.z,mk1.w};
            float t[8];
#pragma unroll
            for (int j = 0; j < 8; j++) {
                t[j] = mk[j] ? __expf(s[i][j] * 0.125f) : 0.f;
                l_i[i] += t[j];
            }
            float* Tp = Trow + (size_t)i*S_ + k0;
            *(float4*)Tp       = make_float4(t[0], t[1], t[2], t[3]);
            *(float4*)(Tp + 4) = make_float4(t[4], t[5], t[6], t[7]);
        }
    }

#pragma unroll
    for (int i = 0; i < 4; i++) {
#pragma unroll
        for (int off = 8; off > 0; off >>= 1)
            l_i[i] += __shfl_xor_sync(0xffffffffu, l_i[i], off, 16);
    }
    if (tx == 0) {
#pragma unroll
        for (int i = 0; i < 4; i++)
            g_linv[(size_t)(b*H_ + h)*S_ + q0 + ty*4 + i] = 1.0f / l_i[i];
    }
}

// ---------------- pass 2: p = t*linv, avg_attn, P@V via bf16x3 mma -----------
// grid (4 ksplit, S/64, B), 256 threads (8 warps; warp tile m16 x n32).
// smem: linv[64] | PsH[64][68]u32 | PsL | VtH[4096]u32 (swizzled) | VtL
#define PS_STRIDE 68   // uint32 words per P row (128 bf16 = 64 words + 4 pad)
#define PV_SMEM (256 + 2*64*PS_STRIDE*4 + 2*4096*4)   // 67840

__global__ void __launch_bounds__(256, 1)
attn_pv_k(float* __restrict__ avg_out)
{
    extern __shared__ char smem2[];
    float*    linv_s = (float*)smem2;
    uint32_t* PsH = (uint32_t*)(smem2 + 256);
    uint32_t* PsL = PsH + 64*PS_STRIDE;
    uint32_t* VtH = PsL + 64*PS_STRIDE;
    uint32_t* VtL = VtH + 4096;

    const int tid = threadIdx.x;
    const int lane = tid & 31, wid = tid >> 5;
    const int ks = blockIdx.x;
    const int q0 = blockIdx.y * 64;
    const int b  = blockIdx.z;

    const int wm = (wid & 3) * 16;        // warp row (m) offset
    const int wn = (wid >> 2) * 32;       // warp col (d) offset

    // T/P thread mapping
    const int pr = tid >> 2;              // 0..63
    const int pc = (tid & 3) * 4;         // col base; cols pc + 16*i
    // V pack thread mapping
    const int dv  = lane + 32 * (wid & 1);    // 0..63
    const int k2b = (wid >> 1) * 16;          // 0..48

    float* ctx = &g_ctx[ks][0];

    for (int h = 0; h < H_; h++) {
        __syncthreads();
        if (tid < 64) linv_s[tid] = g_linv[(size_t)(b*H_ + h)*S_ + q0 + tid];

        float acc[4][4];
#pragma unroll
        for (int ni = 0; ni < 4; ni++)
#pragma unroll
            for (int j = 0; j < 4; j++) acc[ni][j] = 0.f;

        for (int kt = 0; kt < 4; kt++) {
            const int k0 = (ks * 4 + kt) * 128;
            __syncthreads();   // smem free (prev mma done / linv visible)

            // ---- pack V tile: Vt[k2][d] = (bf16 pair of V[2k2][d], V[2k2+1][d]) ----
            {
                const float* Vg = g_V + ((size_t)(b*H_ + h)*S_ + k0)*D_ + dv;
#pragma unroll 4
                for (int kk = 0; kk < 16; kk++) {
                    const int k2 = k2b + kk;
                    float v0 = Vg[(size_t)(2*k2) * D_];
                    float v1 = Vg[(size_t)(2*k2+1) * D_];
                    __nv_bfloat16 h0 = __float2bfloat16(v0);
                    __nv_bfloat16 h1 = __float2bfloat16(v1);
                    float l0 = v0 - __bfloat162float(h0);
                    float l1 = v1 - __bfloat162float(h1);
                    uint32_t off = k2 * 64 + (dv ^ ((k2 & 3) << 3));
                    VtH[off] = (uint32_t)__bfloat16_as_ushort(h0) |
                               ((uint32_t)__bfloat16_as_ushort(h1) << 16);
                    VtL[off] = pack_bf2(l0, l1);
                }
            }

            // ---- load T, p = t*linv, avg accumulate, split to PsH/PsL ----
            {
                const float* Tp = g_T + ((size_t)(b*H_ + h)*S_ + q0 + pr)*S_ + k0;
                float* ap = avg_out + (size_t)b*S_*S_ + (size_t)(q0 + pr)*S_ + k0;
                const float li = linv_s[pr];
#pragma unroll
                for (int i = 0; i < 8; i++) {
                    const int c = pc + 16*i;
                    float4 t4 = *(const float4*)(Tp + c);
                    float p0 = t4.x * li, p1 = t4.y * li, p2 = t4.z * li, p3 = t4.w * li;
                    float4 w = make_float4(p0*0.0625f, p1*0.0625f, p2*0.0625f, p3*0.0625f);
                    if (h != 0) {
                        float4 o = *(const float4*)(ap + c);
                        w.x += o.x; w.y += o.y; w.z += o.z; w.w += o.w;
                    }
                    *(float4*)(ap + c) = w;

                    __nv_bfloat16 h0 = __float2bfloat16(p0), h1 = __float2bfloat16(p1);
                    __nv_bfloat16 h2 = __float2bfloat16(p2), h3 = __float2bfloat16(p3);
                    const int wbase = pr * PS_STRIDE + (c >> 1);
                    PsH[wbase]     = (uint32_t)__bfloat16_as_ushort(h0) |
                                     ((uint32_t)__bfloat16_as_ushort(h1) << 16);
                    PsH[wbase + 1] = (uint32_t)__bfloat16_as_ushort(h2) |
                                     ((uint32_t)__bfloat16_as_ushort(h3) << 16);
                    PsL[wbase]     = pack_bf2(p0 - __bfloat162float(h0),
                                              p1 - __bfloat162float(h1));
                    PsL[wbase + 1] = pack_bf2(p2 - __bfloat162float(h2),
                                              p3 - __bfloat162float(h3));
                }
            }
            __syncthreads();

            // ---- P @ V: 8 k-steps of 16, bf16 split x3 ----
#pragma unroll
            for (int ksi = 0; ksi < 8; ksi++) {
                const int rA = wm + (lane >> 2);
                const int wA = ksi * 8 + (lane & 3);
                uint32_t aH[4], aL[4];
                aH[0] = PsH[rA * PS_STRIDE + wA];
                aH[1] = PsH[(rA + 8) * PS_STRIDE + wA];
                aH[2] = PsH[rA * PS_STRIDE + wA + 4];
                aH[3] = PsH[(rA + 8) * PS_STRIDE + wA + 4];
                aL[0] = PsL[rA * PS_STRIDE + wA];
                aL[1] = PsL[(rA + 8) * PS_STRIDE + wA];
                aL[2] = PsL[rA * PS_STRIDE + wA + 4];
                aL[3] = PsL[(rA + 8) * PS_STRIDE + wA + 4];
                const int k2v = ksi * 8 + (lane & 3);
                const uint32_t sw = (uint32_t)((k2v & 3) << 3);
#pragma unroll
                for (int ni = 0; ni < 4; ni++) {
                    const int n = wn + ni * 8 + (lane >> 2);
                    const uint32_t off0 = k2v * 64 + (n ^ sw);
                    const uint32_t off1 = off0 + 256;   // (k2v+4) row, same swizzle
                    uint32_t b0H = VtH[off0], b1H = VtH[off1];
                    uint32_t b0L = VtL[off0], b1L = VtL[off1];
                    mma_bf16(acc[ni], aH, b0H, b1H);
                    mma_bf16(acc[ni], aH, b0L, b1L);
                    mma_bf16(acc[ni], aL, b0H, b1H);
                }
            }
        }

        // ---- write O slice for this head ----
        const int r0 = b * S_ + q0 + wm + (lane >> 2);
#pragma unroll
        for (int ni = 0; ni < 4; ni++) {
            const int n = h * 64 + wn + ni * 8 + 2 * (lane & 3);
            *(float2*)(ctx + (size_t)r0 * E_ + n)       = make_float2(acc[ni][0], acc[ni][1]);
            *(float2*)(ctx + (size_t)(r0 + 8) * E_ + n) = make_float2(acc[ni][2], acc[ni][3]);
        }
    }
}

// ---------------- launch ----------------------------------------------------
extern "C" void kernel_launch(void* const* d_in, const int* in_sizes, int n_in,
                              void* d_out, int out_size)
{
    const float* query = (const float*)d_in[0];
    const float* key   = (const float*)d_in[1];
    const float* value = (const float*)d_in[2];
    const int*   mask  = (const int*)d_in[3];
    const float* Wq = (const float*)d_in[4];
    const float* bq = (const float*)d_in[5];
    const float* Wk = (const float*)d_in[6];
    const float* bk = (const float*)d_in[7];
    const float* Wv = (const float*)d_in[8];
    const float* bv = (const float*)d_in[9];
    const float* Wo = (const float*)d_in[10];
    const float* bo = (const float*)d_in[11];

    float* out = (float*)d_out;                      // [B,S,E]
    float* avg = out + (size_t)B_*S_*E_;             // [B,S,S]

    float *qp, *kp, *vp, *cp;
    cudaGetSymbolAddress((void**)&qp, g_Q);
    cudaGetSymbolAddress((void**)&kp, g_K);
    cudaGetSymbolAddress((void**)&vp, g_V);
    cudaGetSymbolAddress((void**)&cp, g_ctx);

    cudaFuncSetAttribute(gemm_tf32_k, cudaFuncAttributeMaxDynamicSharedMemorySize, GEMM_SMEM_BYTES);
    cudaFuncSetAttribute(attn_exp_k, cudaFuncAttributeMaxDynamicSharedMemorySize, 49152);
    cudaFuncSetAttribute(attn_pv_k, cudaFuncAttributeMaxDynamicSharedMemorySize, PV_SMEM);

    dim3 ggemm(E_/128, M_/128);   // (8, 32)
    gemm_tf32_k<<<ggemm, 256, GEMM_SMEM_BYTES>>>(query, Wq, bq, qp, 1);
    gemm_tf32_k<<<ggemm, 256, GEMM_SMEM_BYTES>>>(key,   Wk, bk, kp, 1);
    gemm_tf32_k<<<ggemm, 256, GEMM_SMEM_BYTES>>>(value, Wv, bv, vp, 1);

    attn_exp_k<<<dim3(S_/64, H_, B_), 256, 49152>>>(mask);
    attn_pv_k<<<dim3(4, S_/64, B_), 256, PV_SMEM>>>(avg);

    add4_k<<<(M_*E_)/1024, 256>>>();
    gemm_tf32_k<<<ggemm, 256, GEMM_SMEM_BYTES>>>(cp, Wo, bo, out, 0);
}

// round 5
// speedup vs baseline: 2.0201x; 1.5907x over previous
#include <cuda_runtime.h>
#include <cuda_bf16.h>
#include <cstdint>

#define B_ 2
#define S_ 2048
#define E_ 1024
#define H_ 16
#define D_ 64
#define M_ (B_*S_)   // 4096

// ---------------- scratch (device globals; no allocations allowed) ----------
static __device__ float g_Q[(size_t)B_*H_*S_*D_];     // [B,H,S,D]
static __device__ float g_K[(size_t)B_*H_*S_*D_];
static __device__ float g_V[(size_t)B_*H_*S_*D_];
static __device__ float g_linv[(size_t)B_*H_*S_];     // 1 / softmax row sum
static __device__ float g_T[(size_t)B_*H_*S_*S_];     // exp(masked scaled scores), 512 MB
static __device__ float g_ctx[16][(size_t)M_*E_];     // per-ktile partial context

// ===================== PTX helpers (sm_80-era only; no tcgen05) ==============
__device__ __forceinline__ uint32_t smem_u32(const void* p) {
    uint32_t a;
    asm("{ .reg .u64 t; cvta.to.shared.u64 t, %1; cvt.u32.u64 %0, t; }" : "=r"(a) : "l"(p));
    return a;
}
#define CPASYNC16(dst, src) \
    asm volatile("cp.async.cg.shared.global [%0], [%1], 16;" :: "r"(dst), "l"(src))
#define CPCOMMIT() asm volatile("cp.async.commit_group;" ::: "memory")

__device__ __forceinline__ uint32_t f2tf32(float x) {
    uint32_t r;
    asm("cvt.rna.tf32.f32 %0, %1;" : "=r"(r) : "f"(x));
    return r;
}
__device__ __forceinline__ void mma_tf32(float* c, const uint32_t* a, const uint32_t* b) {
    asm volatile(
        "mma.sync.aligned.m16n8k8.row.col.f32.tf32.tf32.f32 "
        "{%0,%1,%2,%3}, {%4,%5,%6,%7}, {%8,%9}, {%0,%1,%2,%3};"
        : "+f"(c[0]), "+f"(c[1]), "+f"(c[2]), "+f"(c[3])
        : "r"(a[0]), "r"(a[1]), "r"(a[2]), "r"(a[3]), "r"(b[0]), "r"(b[1]));
}
__device__ __forceinline__ void mma_bf16(float* c, const uint32_t* a, uint32_t b0, uint32_t b1) {
    asm volatile(
        "mma.sync.aligned.m16n8k16.row.col.f32.bf16.bf16.f32 "
        "{%0,%1,%2,%3}, {%4,%5,%6,%7}, {%8,%9}, {%0,%1,%2,%3};"
        : "+f"(c[0]), "+f"(c[1]), "+f"(c[2]), "+f"(c[3])
        : "r"(a[0]), "r"(a[1]), "r"(a[2]), "r"(a[3]), "r"(b0), "r"(b1));
}
__device__ __forceinline__ uint32_t pack_bf2(float x, float y) {
    __nv_bfloat16 hx = __float2bfloat16(x), hy = __float2bfloat16(y);
    return (uint32_t)__bfloat16_as_ushort(hx) | ((uint32_t)__bfloat16_as_ushort(hy) << 16);
}

// ===================== tf32 mma.sync GEMM: out = A @ W^T + bias ==============
#define BK_ 32
#define PADK 36
#define GEMM_SMEM_BYTES (2 * 2 * 128 * PADK * 4)   // 73728

__global__ void __launch_bounds__(256, 1)
gemm_tf32_k(const float* __restrict__ A, const float* __restrict__ W,
            const float* __restrict__ bias, float* __restrict__ out, int qkv)
{
    extern __shared__ float sgm[];
    float (*As)[128][PADK] = (float(*)[128][PADK])sgm;
    float (*Ws)[128][PADK] = (float(*)[128][PADK])(sgm + 2*128*PADK);

    const int tid = threadIdx.x;
    const int lane = tid & 31, wid = tid >> 5;
    const int wm = (wid & 3) * 32;
    const int wn = (wid >> 2) * 64;
    const int m0 = blockIdx.y * 128;
    const int n0 = blockIdx.x * 128;

    const float* Abase = A + (size_t)m0 * E_;
    const float* Wbase = W + (size_t)n0 * E_;

    const int r_ld = tid >> 1;
    const int c_ld = (tid & 1) * 16;

    auto load_stage = [&](int it, int buf) {
        const float* Ap = Abase + (size_t)r_ld * E_ + it * BK_ + c_ld;
        const float* Wp = Wbase + (size_t)r_ld * E_ + it * BK_ + c_ld;
        uint32_t da = smem_u32(&As[buf][r_ld][c_ld]);
        uint32_t dw = smem_u32(&Ws[buf][r_ld][c_ld]);
#pragma unroll
        for (int i = 0; i < 4; i++) {
            CPASYNC16(da + i * 16, Ap + i * 4);
            CPASYNC16(dw + i * 16, Wp + i * 4);
        }
        CPCOMMIT();
    };

    float acc[2][8][4];
#pragma unroll
    for (int mi = 0; mi < 2; mi++)
#pragma unroll
        for (int ni = 0; ni < 8; ni++)
#pragma unroll
            for (int j = 0; j < 4; j++) acc[mi][ni][j] = 0.f;

    const int NT = E_ / BK_;
    load_stage(0, 0);

    const int qr = lane >> 2;
    const int qc = lane & 3;

    for (int it = 0; it < NT; it++) {
        if (it + 1 < NT) load_stage(it + 1, (it + 1) & 1);
        if (it + 1 < NT) asm volatile("cp.async.wait_group 1;" ::: "memory");
        else             asm volatile("cp.async.wait_group 0;" ::: "memory");
        __syncthreads();

        const int buf = it & 1;
#pragma unroll
        for (int ks = 0; ks < 4; ks++) {
            const int k0 = ks * 8;
            uint32_t a[2][4], b[8][2];
#pragma unroll
            for (int mi = 0; mi < 2; mi++) {
                const int r = wm + mi * 16 + qr;
                a[mi][0] = f2tf32(As[buf][r][k0 + qc]);
                a[mi][1] = f2tf32(As[buf][r + 8][k0 + qc]);
                a[mi][2] = f2tf32(As[buf][r][k0 + qc + 4]);
                a[mi][3] = f2tf32(As[buf][r + 8][k0 + qc + 4]);
            }
#pragma unroll
            for (int ni = 0; ni < 8; ni++) {
                const int n = wn + ni * 8 + qr;
                b[ni][0] = f2tf32(Ws[buf][n][k0 + qc]);
                b[ni][1] = f2tf32(Ws[buf][n][k0 + qc + 4]);
            }
#pragma unroll
            for (int mi = 0; mi < 2; mi++)
#pragma unroll
                for (int ni = 0; ni < 8; ni++)
                    mma_tf32(acc[mi][ni], a[mi], b[ni]);
        }
        __syncthreads();
    }

#pragma unroll
    for (int mi = 0; mi < 2; mi++) {
        const int r0 = m0 + wm + mi * 16 + qr;
#pragma unroll
        for (int ni = 0; ni < 8; ni++) {
            const int n = n0 + wn + ni * 8 + 2 * qc;
            const float b0 = bias[n], b1 = bias[n + 1];
            float2 v0 = make_float2(acc[mi][ni][0] + b0, acc[mi][ni][1] + b1);
            float2 v1 = make_float2(acc[mi][ni][2] + b0, acc[mi][ni][3] + b1);
            if (qkv) {
                const int h = n >> 6, d = n & 63;
                const int bb0 = r0 >> 11, ss0 = r0 & (S_ - 1);
                const int r1 = r0 + 8;
                const int bb1 = r1 >> 11, ss1 = r1 & (S_ - 1);
                *(float2*)(out + (((size_t)(bb0 * H_ + h) * S_ + ss0) * D_ + d)) = v0;
                *(float2*)(out + (((size_t)(bb1 * H_ + h) * S_ + ss1) * D_ + d)) = v1;
            } else {
                *(float2*)(out + (size_t)r0 * E_ + n) = v0;
                *(float2*)(out + (size_t)(r0 + 8) * E_ + n) = v1;
            }
        }
    }
}

// ---------------- ctx0 += ctx1..ctx15 ---------------------------------------
__global__ void __launch_bounds__(256) add16_k()
{
    const size_t i = ((size_t)blockIdx.x * 256 + threadIdx.x) * 4;
    float4 x = *(const float4*)(&g_ctx[0][i]);
#pragma unroll
    for (int s = 1; s < 16; s++) {
        float4 a = *(const float4*)(&g_ctx[s][i]);
        x.x += a.x; x.y += a.y; x.z += a.z; x.w += a.w;
    }
    *(float4*)(&g_ctx[0][i]) = x;
}

// ---------------- pass 1: QK^T (fp32 FFMA) + exp + row-sum -------------------
__global__ void __launch_bounds__(256) attn_exp_k(const int* __restrict__ mask)
{
    extern __shared__ float sm[];
    float* Qs = sm;            // [64][64]  transposed: Qs[d*64 + r]
    float* Ks = sm + 64*64;    // [64][128] transposed: Ks[d*128 + c]

    const int tid = threadIdx.x;
    const int tx = tid & 15, ty = tid >> 4;
    const int q0 = blockIdx.x * 64;
    const int h  = blockIdx.y;
    const int b  = blockIdx.z;

    const float* Qg = g_Q + ((size_t)(b*H_ + h)*S_ + q0)*D_;
    const float* Kg = g_K + ((size_t)(b*H_ + h)*S_)*D_;

    {   // load Q tile transposed
        const int r  = tid >> 2;
        const int d0 = (tid & 3) * 16;
#pragma unroll
        for (int i = 0; i < 4; i++) {
            float4 v = *(const float4*)(Qg + (size_t)r*D_ + d0 + i*4);
            Qs[(d0+i*4+0)*64 + r] = v.x;
            Qs[(d0+i*4+1)*64 + r] = v.y;
            Qs[(d0+i*4+2)*64 + r] = v.z;
            Qs[(d0+i*4+3)*64 + r] = v.w;
        }
    }

    float l_i[4] = {0.f, 0.f, 0.f, 0.f};
    const int* mrow = mask + (size_t)b*S_*S_ + (size_t)(q0 + ty*4)*S_ + tx*8;
    float* Trow = g_T + ((size_t)(b*H_ + h)*S_ + q0 + ty*4)*S_ + tx*8;

    for (int kt = 0; kt < 16; kt++) {
        const int k0 = kt * 128;
        __syncthreads();
        {   // load K tile transposed
            const int r  = tid >> 1;
            const int d0 = (tid & 1) * 32;
#pragma unroll
            for (int i = 0; i < 8; i++) {
                float4 v = *(const float4*)(Kg + (size_t)(k0+r)*D_ + d0 + i*4);
                Ks[(d0+i*4+0)*128 + r] = v.x;
                Ks[(d0+i*4+1)*128 + r] = v.y;
                Ks[(d0+i*4+2)*128 + r] = v.z;
                Ks[(d0+i*4+3)*128 + r] = v.w;
            }
        }
        __syncthreads();

        float s[4][8];
#pragma unroll
        for (int i = 0; i < 4; i++)
#pragma unroll
            for (int j = 0; j < 8; j++) s[i][j] = 0.f;

#pragma unroll 16
        for (int d = 0; d < 64; d++) {
            float4 af = *(const float4*)(Qs + d*64 + ty*4);
            float4 b0 = *(const float4*)(Ks + d*128 + tx*8);
            float4 b1 = *(const float4*)(Ks + d*128 + tx*8 + 4);
            float a[4] = {af.x, af.y, af.z, af.w};
            float bv[8] = {b0.x,b0.y,b0.z,b0.w,b1.x,b1.y,b1.z,b1.w};
#pragma unroll
            for (int i = 0; i < 4; i++)
#pragma unroll
                for (int j = 0; j < 8; j++)
                    s[i][j] = fmaf(a[i], bv[j], s[i][j]);
        }

#pragma unroll
        for (int i = 0; i < 4; i++) {
            int4 mk0 = *(const int4*)(mrow + (size_t)i*S_ + k0);
            int4 mk1 = *(const int4*)(mrow + (size_t)i*S_ + k0 + 4);
            int mk[8] = {mk0.x,mk0.y,mk0.z,mk0.w,mk1.x,mk1.y,mk1.z,mk1.w};
            float t[8];
#pragma unroll
            for (int j = 0; j < 8; j++) {
                t[j] = mk[j] ? __expf(s[i][j] * 0.125f) : 0.f;
                l_i[i] += t[j];
            }
            float* Tp = Trow + (size_t)i*S_ + k0;
            *(float4*)Tp       = make_float4(t[0], t[1], t[2], t[3]);
            *(float4*)(Tp + 4) = make_float4(t[4], t[5], t[6], t[7]);
        }
    }

#pragma unroll
    for (int i = 0; i < 4; i++) {
#pragma unroll
        for (int off = 8; off > 0; off >>= 1)
            l_i[i] += __shfl_xor_sync(0xffffffffu, l_i[i], off, 16);
    }
    if (tx == 0) {
#pragma unroll
        for (int i = 0; i < 4; i++)
            g_linv[(size_t)(b*H_ + h)*S_ + q0 + ty*4 + i] = 1.0f / l_i[i];
    }
}

// ---------------- pass 2: p = t*linv, avg in registers, P@V bf16x3 -----------
// grid (16 ktile, S/64, B), 256 threads. Heads looped inside:
// avg_attn patch lives in registers across heads, written once.
// O partials per (head, ktile) go to g_ctx[kt].
#define PS_STRIDE 68
#define PV_SMEM (256 + 2*64*PS_STRIDE*4 + 2*4096*4)   // 67840

__global__ void __launch_bounds__(256, 1)
attn_pv_k(float* __restrict__ avg_out)
{
    extern __shared__ char smem2[];
    float*    linv_s = (float*)smem2;
    uint32_t* PsH = (uint32_t*)(smem2 + 256);
    uint32_t* PsL = PsH + 64*PS_STRIDE;
    uint32_t* VtH = PsL + 64*PS_STRIDE;
    uint32_t* VtL = VtH + 4096;

    const int tid = threadIdx.x;
    const int lane = tid & 31, wid = tid >> 5;
    const int kt = blockIdx.x;
    const int k0 = kt * 128;
    const int q0 = blockIdx.y * 64;
    const int b  = blockIdx.z;

    const int wm = (wid & 3) * 16;        // warp row (m) offset
    const int wn = (wid >> 2) * 32;       // warp col (d) offset

    const int pr = tid >> 2;              // 0..63
    const int pc = (tid & 3) * 4;         // col base; cols pc + 16*i
    const int dv  = lane + 32 * (wid & 1);    // 0..63
    const int k2b = (wid >> 1) * 16;          // 0..48

    float* ctx = &g_ctx[kt][0];

    float4 avg4[8];
#pragma unroll
    for (int i = 0; i < 8; i++) avg4[i] = make_float4(0.f, 0.f, 0.f, 0.f);

    for (int h = 0; h < H_; h++) {
        __syncthreads();   // prev head's mma done with Ps/Vt; linv_s free
        if (tid < 64) linv_s[tid] = g_linv[(size_t)(b*H_ + h)*S_ + q0 + tid];

        // ---- pack V tile: Vt[k2][d] = bf16 pair (V[2k2][d], V[2k2+1][d]) ----
        {
            const float* Vg = g_V + ((size_t)(b*H_ + h)*S_ + k0)*D_ + dv;
#pragma unroll 4
            for (int kk = 0; kk < 16; kk++) {
                const int k2 = k2b + kk;
                float v0 = Vg[(size_t)(2*k2) * D_];
                float v1 = Vg[(size_t)(2*k2+1) * D_];
                __nv_bfloat16 h0 = __float2bfloat16(v0);
                __nv_bfloat16 h1 = __float2bfloat16(v1);
                float l0 = v0 - __bfloat162float(h0);
                float l1 = v1 - __bfloat162float(h1);
                uint32_t off = k2 * 64 + (dv ^ ((k2 & 3) << 3));
                VtH[off] = (uint32_t)__bfloat16_as_ushort(h0) |
                           ((uint32_t)__bfloat16_as_ushort(h1) << 16);
                VtL[off] = pack_bf2(l0, l1);
            }
        }
        __syncthreads();   // linv_s + Vt visible

        // ---- load T, p = t*linv, avg (registers), split into PsH/PsL ----
        {
            const float* Tp = g_T + ((size_t)(b*H_ + h)*S_ + q0 + pr)*S_ + k0;
            const float li = linv_s[pr];
#pragma unroll
            for (int i = 0; i < 8; i++) {
                const int c = pc + 16*i;
                float4 t4 = *(const float4*)(Tp + c);
                float p0 = t4.x * li, p1 = t4.y * li, p2 = t4.z * li, p3 = t4.w * li;
                avg4[i].x += p0 * 0.0625f;
                avg4[i].y += p1 * 0.0625f;
                avg4[i].z += p2 * 0.0625f;
                avg4[i].w += p3 * 0.0625f;

                __nv_bfloat16 h0 = __float2bfloat16(p0), h1 = __float2bfloat16(p1);
                __nv_bfloat16 h2 = __float2bfloat16(p2), h3 = __float2bfloat16(p3);
                const int wbase = pr * PS_STRIDE + (c >> 1);
                PsH[wbase]     = (uint32_t)__bfloat16_as_ushort(h0) |
                                 ((uint32_t)__bfloat16_as_ushort(h1) << 16);
                PsH[wbase + 1] = (uint32_t)__bfloat16_as_ushort(h2) |
                                 ((uint32_t)__bfloat16_as_ushort(h3) << 16);
                PsL[wbase]     = pack_bf2(p0 - __bfloat162float(h0),
                                          p1 - __bfloat162float(h1));
                PsL[wbase + 1] = pack_bf2(p2 - __bfloat162float(h2),
                                          p3 - __bfloat162float(h3));
            }
        }
        __syncthreads();   // Ps visible

        // ---- P @ V: 8 k-steps of 16, bf16 split x3 ----
        float acc[4][4];
#pragma unroll
        for (int ni = 0; ni < 4; ni++)
#pragma unroll
            for (int j = 0; j < 4; j++) acc[ni][j] = 0.f;

#pragma unroll
        for (int ksi = 0; ksi < 8; ksi++) {
            const int rA = wm + (lane >> 2);
            const int wA = ksi * 8 + (lane & 3);
            uint32_t aH[4], aL[4];
            aH[0] = PsH[rA * PS_STRIDE + wA];
            aH[1] = PsH[(rA + 8) * PS_STRIDE + wA];
            aH[2] = PsH[rA * PS_STRIDE + wA + 4];
            aH[3] = PsH[(rA + 8) * PS_STRIDE + wA + 4];
            aL[0] = PsL[rA * PS_STRIDE + wA];
            aL[1] = PsL[(rA + 8) * PS_STRIDE + wA];
            aL[2] = PsL[rA * PS_STRIDE + wA + 4];
            aL[3] = PsL[(rA + 8) * PS_STRIDE + wA + 4];
            const int k2v = ksi * 8 + (lane & 3);
            const uint32_t sw = (uint32_t)((k2v & 3) << 3);
#pragma unroll
            for (int ni = 0; ni < 4; ni++) {
                const int n = wn + ni * 8 + (lane >> 2);
                const uint32_t off0 = k2v * 64 + (n ^ sw);
                const uint32_t off1 = off0 + 256;   // (k2v+4) row, same swizzle
                uint32_t b0H = VtH[off0], b1H = VtH[off1];
                uint32_t b0L = VtL[off0], b1L = VtL[off1];
                mma_bf16(acc[ni], aH, b0H, b1H);
                mma_bf16(acc[ni], aH, b0L, b1L);
                mma_bf16(acc[ni], aL, b0H, b1H);
            }
        }

        // ---- write O partial for this (head, ktile) ----
        const int r0 = b * S_ + q0 + wm + (lane >> 2);
#pragma unroll
        for (int ni = 0; ni < 4; ni++) {
            const int n = h * 64 + wn + ni * 8 + 2 * (lane & 3);
            *(float2*)(ctx + (size_t)r0 * E_ + n)       = make_float2(acc[ni][0], acc[ni][1]);
            *(float2*)(ctx + (size_t)(r0 + 8) * E_ + n) = make_float2(acc[ni][2], acc[ni][3]);
        }
    }

    // ---- single write of avg patch ----
    {
        float* ap = avg_out + (size_t)b*S_*S_ + (size_t)(q0 + pr)*S_ + k0;
#pragma unroll
        for (int i = 0; i < 8; i++)
            *(float4*)(ap + pc + 16*i) = avg4[i];
    }
}

// ---------------- launch ----------------------------------------------------
extern "C" void kernel_launch(void* const* d_in, const int* in_sizes, int n_in,
                              void* d_out, int out_size)
{
    const float* query = (const float*)d_in[0];
    const float* key   = (const float*)d_in[1];
    const float* value = (const float*)d_in[2];
    const int*   mask  = (const int*)d_in[3];
    const float* Wq = (const float*)d_in[4];
    const float* bq = (const float*)d_in[5];
    const float* Wk = (const float*)d_in[6];
    const float* bk = (const float*)d_in[7];
    const float* Wv = (const float*)d_in[8];
    const float* bv = (const float*)d_in[9];
    const float* Wo = (const float*)d_in[10];
    const float* bo = (const float*)d_in[11];

    float* out = (float*)d_out;                      // [B,S,E]
    float* avg = out + (size_t)B_*S_*E_;             // [B,S,S]

    float *qp, *kp, *vp, *cp;
    cudaGetSymbolAddress((void**)&qp, g_Q);
    cudaGetSymbolAddress((void**)&kp, g_K);
    cudaGetSymbolAddress((void**)&vp, g_V);
    cudaGetSymbolAddress((void**)&cp, g_ctx);

    cudaFuncSetAttribute(gemm_tf32_k, cudaFuncAttributeMaxDynamicSharedMemorySize, GEMM_SMEM_BYTES);
    cudaFuncSetAttribute(attn_exp_k, cudaFuncAttributeMaxDynamicSharedMemorySize, 49152);
    cudaFuncSetAttribute(attn_pv_k, cudaFuncAttributeMaxDynamicSharedMemorySize, PV_SMEM);

    dim3 ggemm(E_/128, M_/128);   // (8, 32)
    gemm_tf32_k<<<ggemm, 256, GEMM_SMEM_BYTES>>>(query, Wq, bq, qp, 1);
    gemm_tf32_k<<<ggemm, 256, GEMM_SMEM_BYTES>>>(key,   Wk, bk, kp, 1);
    gemm_tf32_k<<<ggemm, 256, GEMM_SMEM_BYTES>>>(value, Wv, bv, vp, 1);

    attn_exp_k<<<dim3(S_/64, H_, B_), 256, 49152>>>(mask);
    attn_pv_k<<<dim3(16, S_/64, B_), 256, PV_SMEM>>>(avg);

    add16_k<<<(M_*E_)/1024, 256>>>();
    gemm_tf32_k<<<ggemm, 256, GEMM_SMEM_BYTES>>>(cp, Wo, bo, out, 0);
}

// round 6
// speedup vs baseline: 2.5855x; 1.2799x over previous
#include <cuda_runtime.h>
#include <cuda_bf16.h>
#include <cstdint>

#define B_ 2
#define S_ 2048
#define E_ 1024
#define H_ 16
#define D_ 64
#define M_ (B_*S_)   // 4096

// ---------------- scratch (device globals; no allocations allowed) ----------
static __device__ float g_Q[(size_t)B_*H_*S_*D_];     // [B,H,S,D]
static __device__ float g_K[(size_t)B_*H_*S_*D_];
static __device__ float g_V[(size_t)B_*H_*S_*D_];
static __device__ float g_linv[(size_t)B_*H_*S_];     // 1 / softmax row sum
static __device__ float g_T[(size_t)B_*H_*S_*S_];     // exp(masked scaled scores)
static __device__ float g_ctx[16][(size_t)M_*E_];     // per-ktile partial context

// ===================== PTX helpers (sm_80-era only; no tcgen05) ==============
__device__ __forceinline__ uint32_t smem_u32(const void* p) {
    uint32_t a;
    asm("{ .reg .u64 t; cvta.to.shared.u64 t, %1; cvt.u32.u64 %0, t; }" : "=r"(a) : "l"(p));
    return a;
}
#define CPASYNC16(dst, src) \
    asm volatile("cp.async.cg.shared.global [%0], [%1], 16;" :: "r"(dst), "l"(src))
#define CPCOMMIT() asm volatile("cp.async.commit_group;" ::: "memory")

__device__ __forceinline__ uint32_t f2tf32(float x) {
    uint32_t r;
    asm("cvt.rna.tf32.f32 %0, %1;" : "=r"(r) : "f"(x));
    return r;
}
__device__ __forceinline__ void mma_tf32(float* c, const uint32_t* a, const uint32_t* b) {
    asm volatile(
        "mma.sync.aligned.m16n8k8.row.col.f32.tf32.tf32.f32 "
        "{%0,%1,%2,%3}, {%4,%5,%6,%7}, {%8,%9}, {%0,%1,%2,%3};"
        : "+f"(c[0]), "+f"(c[1]), "+f"(c[2]), "+f"(c[3])
        : "r"(a[0]), "r"(a[1]), "r"(a[2]), "r"(a[3]), "r"(b[0]), "r"(b[1]));
}
__device__ __forceinline__ void mma_bf16(float* c, const uint32_t* a, uint32_t b0, uint32_t b1) {
    asm volatile(
        "mma.sync.aligned.m16n8k16.row.col.f32.bf16.bf16.f32 "
        "{%0,%1,%2,%3}, {%4,%5,%6,%7}, {%8,%9}, {%0,%1,%2,%3};"
        : "+f"(c[0]), "+f"(c[1]), "+f"(c[2]), "+f"(c[3])
        : "r"(a[0]), "r"(a[1]), "r"(a[2]), "r"(a[3]), "r"(b0), "r"(b1));
}
__device__ __forceinline__ uint32_t pack_bf2(float x, float y) {
    __nv_bfloat16 hx = __float2bfloat16(x), hy = __float2bfloat16(y);
    return (uint32_t)__bfloat16_as_ushort(hx) | ((uint32_t)__bfloat16_as_ushort(hy) << 16);
}
// split a float2 into packed bf16 hi and residual lo words
__device__ __forceinline__ void split2(float2 v, uint32_t& hi, uint32_t& lo) {
    __nv_bfloat16 hx = __float2bfloat16(v.x), hy = __float2bfloat16(v.y);
    hi = (uint32_t)__bfloat16_as_ushort(hx) | ((uint32_t)__bfloat16_as_ushort(hy) << 16);
    lo = pack_bf2(v.x - __bfloat162float(hx), v.y - __bfloat162float(hy));
}

// ===================== tf32 mma.sync GEMM core: out = A @ W^T + bias =========
#define BK_ 32
#define PADK 36
#define GEMM_SMEM_BYTES (2 * 2 * 128 * PADK * 4)   // 73728

template<int SCATTER>
__device__ __forceinline__ void gemm_core(float* sgm,
    const float* __restrict__ A, const float* __restrict__ W,
    const float* __restrict__ bias, float* __restrict__ out)
{
    float (*As)[128][PADK] = (float(*)[128][PADK])sgm;
    float (*Ws)[128][PADK] = (float(*)[128][PADK])(sgm + 2*128*PADK);

    const int tid = threadIdx.x;
    const int lane = tid & 31, wid = tid >> 5;
    const int wm = (wid & 3) * 32;
    const int wn = (wid >> 2) * 64;
    const int m0 = blockIdx.y * 128;
    const int n0 = blockIdx.x * 128;

    const float* Abase = A + (size_t)m0 * E_;
    const float* Wbase = W + (size_t)n0 * E_;

    const int r_ld = tid >> 1;
    const int c_ld = (tid & 1) * 16;

    auto load_stage = [&](int it, int buf) {
        const float* Ap = Abase + (size_t)r_ld * E_ + it * BK_ + c_ld;
        const float* Wp = Wbase + (size_t)r_ld * E_ + it * BK_ + c_ld;
        uint32_t da = smem_u32(&As[buf][r_ld][c_ld]);
        uint32_t dw = smem_u32(&Ws[buf][r_ld][c_ld]);
#pragma unroll
        for (int i = 0; i < 4; i++) {
            CPASYNC16(da + i * 16, Ap + i * 4);
            CPASYNC16(dw + i * 16, Wp + i * 4);
        }
        CPCOMMIT();
    };

    float acc[2][8][4];
#pragma unroll
    for (int mi = 0; mi < 2; mi++)
#pragma unroll
        for (int ni = 0; ni < 8; ni++)
#pragma unroll
            for (int j = 0; j < 4; j++) acc[mi][ni][j] = 0.f;

    const int NT = E_ / BK_;
    load_stage(0, 0);

    const int qr = lane >> 2;
    const int qc = lane & 3;

    for (int it = 0; it < NT; it++) {
        if (it + 1 < NT) load_stage(it + 1, (it + 1) & 1);
        if (it + 1 < NT) asm volatile("cp.async.wait_group 1;" ::: "memory");
        else             asm volatile("cp.async.wait_group 0;" ::: "memory");
        __syncthreads();

        const int buf = it & 1;
#pragma unroll
        for (int ks = 0; ks < 4; ks++) {
            const int k0 = ks * 8;
            uint32_t a[2][4], b[8][2];
#pragma unroll
            for (int mi = 0; mi < 2; mi++) {
                const int r = wm + mi * 16 + qr;
                a[mi][0] = f2tf32(As[buf][r][k0 + qc]);
                a[mi][1] = f2tf32(As[buf][r + 8][k0 + qc]);
                a[mi][2] = f2tf32(As[buf][r][k0 + qc + 4]);
                a[mi][3] = f2tf32(As[buf][r + 8][k0 + qc + 4]);
            }
#pragma unroll
            for (int ni = 0; ni < 8; ni++) {
                const int n = wn + ni * 8 + qr;
                b[ni][0] = f2tf32(Ws[buf][n][k0 + qc]);
                b[ni][1] = f2tf32(Ws[buf][n][k0 + qc + 4]);
            }
#pragma unroll
            for (int mi = 0; mi < 2; mi++)
#pragma unroll
                for (int ni = 0; ni < 8; ni++)
                    mma_tf32(acc[mi][ni], a[mi], b[ni]);
        }
        __syncthreads();
    }

#pragma unroll
    for (int mi = 0; mi < 2; mi++) {
        const int r0 = m0 + wm + mi * 16 + qr;
#pragma unroll
        for (int ni = 0; ni < 8; ni++) {
            const int n = n0 + wn + ni * 8 + 2 * qc;
            const float b0 = bias[n], b1 = bias[n + 1];
            float2 v0 = make_float2(acc[mi][ni][0] + b0, acc[mi][ni][1] + b1);
            float2 v1 = make_float2(acc[mi][ni][2] + b0, acc[mi][ni][3] + b1);
            if (SCATTER) {
                const int h = n >> 6, d = n & 63;
                const int bb0 = r0 >> 11, ss0 = r0 & (S_ - 1);
                const int r1 = r0 + 8;
                const int bb1 = r1 >> 11, ss1 = r1 & (S_ - 1);
                *(float2*)(out + (((size_t)(bb0 * H_ + h) * S_ + ss0) * D_ + d)) = v0;
                *(float2*)(out + (((size_t)(bb1 * H_ + h) * S_ + ss1) * D_ + d)) = v1;
            } else {
                *(float2*)(out + (size_t)r0 * E_ + n) = v0;
                *(float2*)(out + (size_t)(r0 + 8) * E_ + n) = v1;
            }
        }
    }
}

struct QKVArgs {
    const float *A0, *A1, *A2;
    const float *W0, *W1, *W2;
    const float *b0, *b1, *b2;
    float *o0, *o1, *o2;
};

__global__ void __launch_bounds__(256, 1)
gemm_qkv_k(QKVArgs a)
{
    extern __shared__ float sgm[];
    const int z = blockIdx.z;
    const float* A = (z == 0) ? a.A0 : (z == 1) ? a.A1 : a.A2;
    const float* W = (z == 0) ? a.W0 : (z == 1) ? a.W1 : a.W2;
    const float* bias = (z == 0) ? a.b0 : (z == 1) ? a.b1 : a.b2;
    float* out = (z == 0) ? a.o0 : (z == 1) ? a.o1 : a.o2;
    gemm_core<1>(sgm, A, W, bias, out);
}

__global__ void __launch_bounds__(256, 1)
gemm_o_k(const float* __restrict__ A, const float* __restrict__ W,
         const float* __restrict__ bias, float* __restrict__ out)
{
    extern __shared__ float sgm[];
    gemm_core<0>(sgm, A, W, bias, out);
}

// ---------------- ctx0 += ctx1..ctx15 ---------------------------------------
__global__ void __launch_bounds__(256) add16_k()
{
    const size_t i = ((size_t)blockIdx.x * 256 + threadIdx.x) * 4;
    float4 x = *(const float4*)(&g_ctx[0][i]);
#pragma unroll
    for (int s = 1; s < 16; s++) {
        float4 a = *(const float4*)(&g_ctx[s][i]);
        x.x += a.x; x.y += a.y; x.z += a.z; x.w += a.w;
    }
    *(float4*)(&g_ctx[0][i]) = x;
}

// ---------------- pass 1: QK^T via bf16x3 mma + exp + row-sum ----------------
// grid (S/64, H, B), 256 threads (8 warps: 4 row groups x 2 col groups).
// Q fragments live in registers (reused over 16 k-tiles); K tiles staged in
// smem as packed bf16 (hi,lo) uint2 with XOR swizzle (conflict-free frag loads).
__global__ void __launch_bounds__(256) attn_exp_k(const int* __restrict__ mask)
{
    __shared__ uint2 Kt[4096];       // [n=128][w=32] packed (hi,lo), swizzled
    __shared__ float rowsum[64];

    const int tid = threadIdx.x;
    const int lane = tid & 31, wid = tid >> 5;
    const int gid = lane >> 2, tig = lane & 3;
    const int q0 = blockIdx.x * 64;
    const int h = blockIdx.y, b = blockIdx.z;
    const int bh = b * H_ + h;
    const int wm = (wid & 3) * 16;      // warp q-row offset
    const int wn = (wid >> 2) * 64;     // warp k-col offset

    if (tid < 64) rowsum[tid] = 0.f;

    // ---- Q fragments (bf16 hi/lo) for rows wm+gid, wm+8+gid ----
    uint32_t aH[4][4], aL[4][4];
    {
        const float* Qg = g_Q + ((size_t)bh * S_ + q0 + wm) * D_;
#pragma unroll
        for (int ks = 0; ks < 4; ks++) {
            const int d0 = ks * 16 + 2 * tig;
            float2 v00 = *(const float2*)(Qg + (size_t)gid * D_ + d0);
            float2 v10 = *(const float2*)(Qg + (size_t)(gid + 8) * D_ + d0);
            float2 v01 = *(const float2*)(Qg + (size_t)gid * D_ + d0 + 8);
            float2 v11 = *(const float2*)(Qg + (size_t)(gid + 8) * D_ + d0 + 8);
            split2(v00, aH[ks][0], aL[ks][0]);
            split2(v10, aH[ks][1], aL[ks][1]);
            split2(v01, aH[ks][2], aL[ks][2]);
            split2(v11, aH[ks][3], aL[ks][3]);
        }
    }

    float lsum0 = 0.f, lsum1 = 0.f;
    const float* Kg = g_K + (size_t)bh * S_ * D_;
    const int r0 = q0 + wm + gid;
    const int* mrow0 = mask + (size_t)b * S_ * S_ + (size_t)r0 * S_;
    float* T0 = g_T + ((size_t)bh * S_ + r0) * S_;

    for (int kt = 0; kt < 16; kt++) {
        const int k0 = kt * 128;
        __syncthreads();
        // ---- stage K tile (128 keys x 64 d) packed bf16 hi/lo ----
#pragma unroll
        for (int rp = 0; rp < 2; rp++) {
            const int n = rp * 64 + (tid >> 2);
            const int q = tid & 3;
            const float* Kp = Kg + (size_t)(k0 + n) * D_ + q * 16;
            const uint32_t sw = (uint32_t)((n & 7) << 2);
#pragma unroll
            for (int j = 0; j < 4; j++) {
                float4 v = *(const float4*)(Kp + j * 4);
                const int w = q * 8 + j * 2;
                uint32_t h0, l0, h1, l1;
                split2(make_float2(v.x, v.y), h0, l0);
                split2(make_float2(v.z, v.w), h1, l1);
                Kt[n * 32 + (w ^ sw)]       = make_uint2(h0, l0);
                Kt[n * 32 + ((w + 1) ^ sw)] = make_uint2(h1, l1);
            }
        }
        __syncthreads();

        // ---- S = Q @ K^T via bf16 split x3 ----
        float s[8][4];
#pragma unroll
        for (int ni = 0; ni < 8; ni++)
#pragma unroll
            for (int j = 0; j < 4; j++) s[ni][j] = 0.f;

#pragma unroll
        for (int ks = 0; ks < 4; ks++) {
#pragma unroll
            for (int ni = 0; ni < 8; ni++) {
                const int nl = wn + ni * 8 + gid;
                const uint32_t sw = (uint32_t)(gid << 2);
                uint2 kv0 = Kt[nl * 32 + ((ks * 8 + tig) ^ sw)];
                uint2 kv1 = Kt[nl * 32 + ((ks * 8 + tig + 4) ^ sw)];
                mma_bf16(s[ni], aH[ks], kv0.x, kv1.x);
                mma_bf16(s[ni], aH[ks], kv0.y, kv1.y);
                mma_bf16(s[ni], aL[ks], kv0.x, kv1.x);
            }
        }

        // ---- mask, exp, store T, accumulate row sums ----
#pragma unroll
        for (int ni = 0; ni < 8; ni++) {
            const int col = k0 + wn + ni * 8 + 2 * tig;
            int2 m0 = *(const int2*)(mrow0 + col);
            int2 m1 = *(const int2*)(mrow0 + 8 * S_ + col);
            float t00 = m0.x ? __expf(s[ni][0] * 0.125f) : 0.f;
            float t01 = m0.y ? __expf(s[ni][1] * 0.125f) : 0.f;
            float t10 = m1.x ? __expf(s[ni][2] * 0.125f) : 0.f;
            float t11 = m1.y ? __expf(s[ni][3] * 0.125f) : 0.f;
            *(float2*)(T0 + col)           = make_float2(t00, t01);
            *(float2*)(T0 + 8 * S_ + col)  = make_float2(t10, t11);
            lsum0 += t00 + t01;
            lsum1 += t10 + t11;
        }
    }

    lsum0 += __shfl_xor_sync(0xffffffffu, lsum0, 1);
    lsum0 += __shfl_xor_sync(0xffffffffu, lsum0, 2);
    lsum1 += __shfl_xor_sync(0xffffffffu, lsum1, 1);
    lsum1 += __shfl_xor_sync(0xffffffffu, lsum1, 2);
    if (tig == 0) {
        atomicAdd(&rowsum[wm + gid], lsum0);
        atomicAdd(&rowsum[wm + 8 + gid], lsum1);
    }
    __syncthreads();
    if (tid < 64)
        g_linv[(size_t)bh * S_ + q0 + tid] = 1.0f / rowsum[tid];
}

// ---------------- pass 2: p = t*linv, avg in registers, P@V bf16x3 -----------
#define PS_STRIDE 68
#define PV_SMEM (256 + 2*64*PS_STRIDE*4 + 2*4096*4)   // 67840

__global__ void __launch_bounds__(256, 1)
attn_pv_k(float* __restrict__ avg_out)
{
    extern __shared__ char smem2[];
    float*    linv_s = (float*)smem2;
    uint32_t* PsH = (uint32_t*)(smem2 + 256);
    uint32_t* PsL = PsH + 64*PS_STRIDE;
    uint32_t* VtH = PsL + 64*PS_STRIDE;
    uint32_t* VtL = VtH + 4096;

    const int tid = threadIdx.x;
    const int lane = tid & 31, wid = tid >> 5;
    const int kt = blockIdx.x;
    const int k0 = kt * 128;
    const int q0 = blockIdx.y * 64;
    const int b  = blockIdx.z;

    const int wm = (wid & 3) * 16;
    const int wn = (wid >> 2) * 32;

    const int pr = tid >> 2;
    const int pc = (tid & 3) * 4;
    const int dv  = lane + 32 * (wid & 1);
    const int k2b = (wid >> 1) * 16;

    float* ctx = &g_ctx[kt][0];

    float4 avg4[8];
#pragma unroll
    for (int i = 0; i < 8; i++) avg4[i] = make_float4(0.f, 0.f, 0.f, 0.f);

    for (int h = 0; h < H_; h++) {
        __syncthreads();
        if (tid < 64) linv_s[tid] = g_linv[(size_t)(b*H_ + h)*S_ + q0 + tid];

        {
            const float* Vg = g_V + ((size_t)(b*H_ + h)*S_ + k0)*D_ + dv;
#pragma unroll 4
            for (int kk = 0; kk < 16; kk++) {
                const int k2 = k2b + kk;
                float v0 = Vg[(size_t)(2*k2) * D_];
                float v1 = Vg[(size_t)(2*k2+1) * D_];
                __nv_bfloat16 h0 = __float2bfloat16(v0);
                __nv_bfloat16 h1 = __float2bfloat16(v1);
                float l0 = v0 - __bfloat162float(h0);
                float l1 = v1 - __bfloat162float(h1);
                uint32_t off = k2 * 64 + (dv ^ ((k2 & 3) << 3));
                VtH[off] = (uint32_t)__bfloat16_as_ushort(h0) |
                           ((uint32_t)__bfloat16_as_ushort(h1) << 16);
                VtL[off] = pack_bf2(l0, l1);
            }
        }
        __syncthreads();

        {
            const float* Tp = g_T + ((size_t)(b*H_ + h)*S_ + q0 + pr)*S_ + k0;
            const float li = linv_s[pr];
#pragma unroll
            for (int i = 0; i < 8; i++) {
                const int c = pc + 16*i;
                float4 t4 = *(const float4*)(Tp + c);
                float p0 = t4.x * li, p1 = t4.y * li, p2 = t4.z * li, p3 = t4.w * li;
                avg4[i].x += p0 * 0.0625f;
                avg4[i].y += p1 * 0.0625f;
                avg4[i].z += p2 * 0.0625f;
                avg4[i].w += p3 * 0.0625f;

                __nv_bfloat16 h0 = __float2bfloat16(p0), h1 = __float2bfloat16(p1);
                __nv_bfloat16 h2 = __float2bfloat16(p2), h3 = __float2bfloat16(p3);
                const int wbase = pr * PS_STRIDE + (c >> 1);
                PsH[wbase]     = (uint32_t)__bfloat16_as_ushort(h0) |
                                 ((uint32_t)__bfloat16_as_ushort(h1) << 16);
                PsH[wbase + 1] = (uint32_t)__bfloat16_as_ushort(h2) |
                                 ((uint32_t)__bfloat16_as_ushort(h3) << 16);
                PsL[wbase]     = pack_bf2(p0 - __bfloat162float(h0),
                                          p1 - __bfloat162float(h1));
                PsL[wbase + 1] = pack_bf2(p2 - __bfloat162float(h2),
                                          p3 - __bfloat162float(h3));
            }
        }
        __syncthreads();

        float acc[4][4];
#pragma unroll
        for (int ni = 0; ni < 4; ni++)
#pragma unroll
            for (int j = 0; j < 4; j++) acc[ni][j] = 0.f;

#pragma unroll
        for (int ksi = 0; ksi < 8; ksi++) {
            const int rA = wm + (lane >> 2);
            const int wA = ksi * 8 + (lane & 3);
            uint32_t aH[4], aL[4];
            aH[0] = PsH[rA * PS_STRIDE + wA];
            aH[1] = PsH[(rA + 8) * PS_STRIDE + wA];
            aH[2] = PsH[rA * PS_STRIDE + wA + 4];
            aH[3] = PsH[(rA + 8) * PS_STRIDE + wA + 4];
            aL[0] = PsL[rA * PS_STRIDE + wA];
            aL[1] = PsL[(rA + 8) * PS_STRIDE + wA];
            aL[2] = PsL[rA * PS_STRIDE + wA + 4];
            aL[3] = PsL[(rA + 8) * PS_STRIDE + wA + 4];
            const int k2v = ksi * 8 + (lane & 3);
            const uint32_t sw = (uint32_t)((k2v & 3) << 3);
#pragma unroll
            for (int ni = 0; ni < 4; ni++) {
                const int n = wn + ni * 8 + (lane >> 2);
                const uint32_t off0 = k2v * 64 + (n ^ sw);
                const uint32_t off1 = off0 + 256;
                uint32_t b0H = VtH[off0], b1H = VtH[off1];
                uint32_t b0L = VtL[off0], b1L = VtL[off1];
                mma_bf16(acc[ni], aH, b0H, b1H);
                mma_bf16(acc[ni], aH, b0L, b1L);
                mma_bf16(acc[ni], aL, b0H, b1H);
            }
        }

        const int r0 = b * S_ + q0 + wm + (lane >> 2);
#pragma unroll
        for (int ni = 0; ni < 4; ni++) {
            const int n = h * 64 + wn + ni * 8 + 2 * (lane & 3);
            *(float2*)(ctx + (size_t)r0 * E_ + n)       = make_float2(acc[ni][0], acc[ni][1]);
            *(float2*)(ctx + (size_t)(r0 + 8) * E_ + n) = make_float2(acc[ni][2], acc[ni][3]);
        }
    }

    {
        float* ap = avg_out + (size_t)b*S_*S_ + (size_t)(q0 + pr)*S_ + k0;
#pragma unroll
        for (int i = 0; i < 8; i++)
            *(float4*)(ap + pc + 16*i) = avg4[i];
    }
}

// ---------------- launch ----------------------------------------------------
extern "C" void kernel_launch(void* const* d_in, const int* in_sizes, int n_in,
                              void* d_out, int out_size)
{
    const float* query = (const float*)d_in[0];
    const float* key   = (const float*)d_in[1];
    const float* value = (const float*)d_in[2];
    const int*   mask  = (const int*)d_in[3];
    const float* Wq = (const float*)d_in[4];
    const float* bq = (const float*)d_in[5];
    const float* Wk = (const float*)d_in[6];
    const float* bk = (const float*)d_in[7];
    const float* Wv = (const float*)d_in[8];
    const float* bv = (const float*)d_in[9];
    const float* Wo = (const float*)d_in[10];
    const float* bo = (const float*)d_in[11];

    float* out = (float*)d_out;                      // [B,S,E]
    float* avg = out + (size_t)B_*S_*E_;             // [B,S,S]

    float *qp, *kp, *vp, *cp;
    cudaGetSymbolAddress((void**)&qp, g_Q);
    cudaGetSymbolAddress((void**)&kp, g_K);
    cudaGetSymbolAddress((void**)&vp, g_V);
    cudaGetSymbolAddress((void**)&cp, g_ctx);

    cudaFuncSetAttribute(gemm_qkv_k, cudaFuncAttributeMaxDynamicSharedMemorySize, GEMM_SMEM_BYTES);
    cudaFuncSetAttribute(gemm_o_k,   cudaFuncAttributeMaxDynamicSharedMemorySize, GEMM_SMEM_BYTES);
    cudaFuncSetAttribute(attn_pv_k,  cudaFuncAttributeMaxDynamicSharedMemorySize, PV_SMEM);

    QKVArgs qa{query, key, value, Wq, Wk, Wv, bq, bk, bv, qp, kp, vp};
    gemm_qkv_k<<<dim3(E_/128, M_/128, 3), 256, GEMM_SMEM_BYTES>>>(qa);

    attn_exp_k<<<dim3(S_/64, H_, B_), 256>>>(mask);
    attn_pv_k<<<dim3(16, S_/64, B_), 256, PV_SMEM>>>(avg);

    add16_k<<<(M_*E_)/1024, 256>>>();
    gemm_o_k<<<dim3(E_/128, M_/128), 256, GEMM_SMEM_BYTES>>>(cp, Wo, bo, out);
}